// round 14
// baseline (speedup 1.0000x reference)
#include <cuda_runtime.h>
#include <cuda_bf16.h>
#include <cuda_fp16.h>
#include <math.h>
#include <stdint.h>

// ---------------- problem constants ----------------
#define B_SZ   256
#define C1     256
#define H1     20
#define C2     256
#define GS     36
#define G_NUM  32
#define PD     8
#define OC     10
#define OD     16
#define KGEMM  (256*81)     // 20736
#define NGEMM  (B_SZ*GS)    // 9216
#define NCHUNK (KGEMM/64)   // 324
#define N1     (B_SZ*400)   // 102400

// ---------------- scratch ----------------
__device__ __nv_bfloat16 g_x1h[(size_t)N1 * C1];
__device__ __nv_bfloat16 g_x1l[(size_t)N1 * C1];
__device__ __nv_bfloat16 g_w1h[(size_t)C1 * 96];
__device__ __nv_bfloat16 g_w1l[(size_t)C1 * 96];
__device__ __nv_bfloat16 g_w2h[(size_t)C1 * KGEMM];
__device__ __nv_bfloat16 g_w2l[(size_t)C1 * KGEMM];
__device__ float  g_y2[(size_t)NGEMM * C2];                 // [(b*36+s)][oc]
__device__ __half g_wth[(size_t)G_NUM * GS * 160 * 8];      // Wcaps^T fp16 [g][s][j][i]
__device__ float  g_vg[(size_t)B_SZ * G_NUM * OC * OD];

// ---------------- helpers ----------------
__device__ __forceinline__ uint32_t smem_u32(const void* p) {
    uint32_t a;
    asm("{ .reg .u64 t; cvta.to.shared.u64 t, %1; cvt.u32.u64 %0, t; }" : "=r"(a) : "l"(p));
    return a;
}
__device__ __forceinline__ void cpasync16(uint32_t dst, const void* src) {
    asm volatile("cp.async.cg.shared.global [%0], [%1], 16;" :: "r"(dst), "l"(src));
}
#define CP_COMMIT()  asm volatile("cp.async.commit_group;" ::: "memory")
#define CP_WAIT(N)   asm volatile("cp.async.wait_group " #N ";" ::: "memory")

__device__ __forceinline__ void ldsm4(uint32_t* r, uint32_t addr) {
    asm volatile("ldmatrix.sync.aligned.m8n8.x4.shared.b16 {%0,%1,%2,%3}, [%4];"
        : "=r"(r[0]), "=r"(r[1]), "=r"(r[2]), "=r"(r[3]) : "r"(addr));
}
__device__ __forceinline__ void mma16816(float* d, const uint32_t* a, const uint32_t* b) {
    asm volatile(
        "mma.sync.aligned.m16n8k16.row.col.f32.bf16.bf16.f32 "
        "{%0,%1,%2,%3}, {%4,%5,%6,%7}, {%8,%9}, {%0,%1,%2,%3};"
        : "+f"(d[0]), "+f"(d[1]), "+f"(d[2]), "+f"(d[3])
        : "r"(a[0]), "r"(a[1]), "r"(a[2]), "r"(a[3]), "r"(b[0]), "r"(b[1]));
}
__device__ __forceinline__ int swz(int byte) { return byte ^ ((byte >> 3) & 0x70); }
__device__ __forceinline__ void pack_hl2(float v0, float v1, uint32_t& o0, uint32_t& o1) {
    __nv_bfloat162 h2v = __floats2bfloat162_rn(v0, v1);
    uint32_t h2 = *(uint32_t*)&h2v;
    float f0 = __uint_as_float(h2 << 16);
    float f1 = __uint_as_float(h2 & 0xFFFF0000u);
    __nv_bfloat162 l2v = __floats2bfloat162_rn(v0 - f0, v1 - f1);
    uint32_t l2 = *(uint32_t*)&l2v;
    o0 = __byte_perm(h2, l2, 0x5410);
    o1 = __byte_perm(h2, l2, 0x7632);
}
__device__ __forceinline__ float dot8h(float4 ua, float4 ub, const __half* w) {
    const __half2* w2 = (const __half2*)w;
    float2 f0 = __half22float2(w2[0]);
    float2 f1 = __half22float2(w2[1]);
    float2 f2 = __half22float2(w2[2]);
    float2 f3 = __half22float2(w2[3]);
    return ua.x*f0.x + ua.y*f0.y + ua.z*f1.x + ua.w*f1.y
         + ub.x*f2.x + ub.y*f2.y + ub.z*f3.x + ub.w*f3.y;
}

// ================= prep: W1 -> bf16 hi/lo padded =================
__global__ void prep_w1(const float* __restrict__ W1) {
    int idx = blockIdx.x * 256 + threadIdx.x;
    if (idx >= C1 * 96) return;
    int oc = idx / 96, k = idx - oc * 96;
    float w = (k < 81) ? W1[oc * 81 + k] : 0.f;
    __nv_bfloat16 h = __float2bfloat16(w);
    g_w1h[idx] = h;
    g_w1l[idx] = __float2bfloat16(w - __bfloat162float(h));
}

// ================= prep: Wcaps -> fp16 transposed [g][s][j][i] =================
__global__ void prep_wt(const float* __restrict__ Wcaps) {
    __shared__ float t[1280];
    const int gs = blockIdx.x;
    const int tid = threadIdx.x;
    for (int f = tid; f < 1280; f += 256) t[f] = Wcaps[(size_t)gs * 1280 + f];
    __syncthreads();
    for (int ff = tid; ff < 640; ff += 256) {
        int f = ff * 2;
        int j = f >> 3, i = f & 7;
        __half2 h = __floats2half2_rn(t[i * 160 + j], t[(i + 1) * 160 + j]);
        *(__half2*)(g_wth + (size_t)gs * 1280 + f) = h;
    }
}

// ================= prep: W2 -> bf16 hi/lo, k' = khw*256+ic =================
__global__ void w2_convert_kernel(const float* __restrict__ W2) {
    extern __shared__ float sw[];
    const int m = blockIdx.x, tid = threadIdx.x;
    for (int i = tid; i < 20736; i += 256) sw[i] = W2[(size_t)m * 20736 + i];
    __syncthreads();
    for (int t = tid; t < 2592; t += 256) {
        int base = t * 8;
        int khw = base >> 8, ic0 = base & 255;
        float v[8];
#pragma unroll
        for (int q = 0; q < 8; ++q) v[q] = sw[(ic0 + q) * 81 + khw];
        uint32_t hp[4], lp[4];
#pragma unroll
        for (int q = 0; q < 4; ++q) {
            __nv_bfloat16 h0 = __float2bfloat16(v[2*q]);
            __nv_bfloat16 h1 = __float2bfloat16(v[2*q+1]);
            __nv_bfloat16 l0 = __float2bfloat16(v[2*q]   - __bfloat162float(h0));
            __nv_bfloat16 l1 = __float2bfloat16(v[2*q+1] - __bfloat162float(h1));
            hp[q] = (uint32_t)__bfloat16_as_ushort(h0) | ((uint32_t)__bfloat16_as_ushort(h1) << 16);
            lp[q] = (uint32_t)__bfloat16_as_ushort(l0) | ((uint32_t)__bfloat16_as_ushort(l1) << 16);
        }
        *(uint4*)(g_w2h + (size_t)m * 20736 + base) = make_uint4(hp[0], hp[1], hp[2], hp[3]);
        *(uint4*)(g_w2l + (size_t)m * 20736 + base) = make_uint4(lp[0], lp[1], lp[2], lp[3]);
    }
}

// ================= conv1: split-3 bf16 HMMA =================
#define C1_IMG   0
#define C1_BASEN 6272
#define C1_AH    7168
#define C1_AL    (C1_AH + 26624)
#define C1_BH    (C1_AL + 26624)
#define C1_BL    (C1_BH + 26624)
#define C1_SMEM  (C1_BL + 26624)     // 113664

// compile-time im2col offset: k -> (k/9)*28 + k%9, invalid (k>=81) -> -1
__device__ __forceinline__ constexpr int c1_off(int k) {
    return (k < 81) ? (k / 9) * 28 + (k % 9) : -1;
}
template<int K0>
__device__ __forceinline__ void c1_bbuild(const float* s_img, int base,
                                          uint32_t* bh, uint32_t* bl) {
#pragma unroll
    for (int kk = 0; kk < 24; ++kk) {
        constexpr int dummy = 0; (void)dummy;
        const int k = K0 + kk * 2;
        const int o0 = c1_off(k), o1 = c1_off(k + 1);
        float v0 = (o0 >= 0) ? s_img[base + o0] : 0.f;
        float v1 = (o1 >= 0) ? s_img[base + o1] : 0.f;
        __nv_bfloat162 h2v = __floats2bfloat162_rn(v0, v1);
        uint32_t h2 = *(uint32_t*)&h2v;
        float f0 = __uint_as_float(h2 << 16);
        float f1 = __uint_as_float(h2 & 0xFFFF0000u);
        __nv_bfloat162 l2v = __floats2bfloat162_rn(v0 - f0, v1 - f1);
        bh[kk] = h2;
        bl[kk] = *(uint32_t*)&l2v;
    }
}

__global__ __launch_bounds__(256, 2) void conv1_mma_kernel(const float* __restrict__ inp,
                                                           const float* __restrict__ b1) {
    extern __shared__ char smem[];
    float* s_img  = (float*)(smem + C1_IMG);
    int*   base_n = (int*)(smem + C1_BASEN);
    const uint32_t sb = smem_u32(smem);
    const int tid = threadIdx.x;
    const int wid = tid >> 5, lane = tid & 31;
    const int n0 = blockIdx.x * 128;
    const int m0 = blockIdx.y * 128;
    const int wm = wid & 1, wn = wid >> 1;
    const int bA = n0 / 400;

    for (int i = tid; i < 1568; i += 256) {
        int bimg = bA + (i >= 784);
        s_img[i] = (bimg < B_SZ) ? inp[bimg * 784 + (i % 784)] : 0.f;
    }
    if (tid < 128) {
        int n = n0 + tid;
        int b = n / 400, r = n - b * 400;
        int oh = r / 20, ow = r - oh * 20;
        base_n[tid] = (b - bA) * 784 + oh * 28 + ow;
    }

    for (int p = 0; p < 6; ++p) {
        int f = tid + p * 256;
        int row = f / 12, seg = f % 12;
        uint4 vh = *(const uint4*)(g_w1h + (size_t)(m0 + row) * 96 + seg * 8);
        uint4 vl = *(const uint4*)(g_w1l + (size_t)(m0 + row) * 96 + seg * 8);
        *(uint4*)(smem + C1_AH + row * 208 + seg * 16) = vh;
        *(uint4*)(smem + C1_AL + row * 208 + seg * 16) = vl;
    }
    __syncthreads();

    // B build with static offsets
    {
        const int row = tid >> 1;
        const int half = tid & 1;
        const int base = base_n[row];
        uint32_t* bh = (uint32_t*)(smem + C1_BH + row * 208) + half * 24;
        uint32_t* bl = (uint32_t*)(smem + C1_BL + row * 208) + half * 24;
        if (half == 0) c1_bbuild<0>(s_img, base, bh, bl);
        else           c1_bbuild<48>(s_img, base, bh, bl);
    }
    __syncthreads();

    const int a_row = lane & 15, a_hi = (lane >> 4) << 4;
    const int b_row = ((lane >> 4) << 3) + (lane & 7), b_hi = ((lane >> 3) & 1) << 4;

    float acc[4][4][4];
#pragma unroll
    for (int i = 0; i < 4; ++i)
#pragma unroll
        for (int j = 0; j < 4; ++j)
#pragma unroll
            for (int r = 0; r < 4; ++r) acc[i][j][r] = 0.f;

#pragma unroll
    for (int ks = 0; ks < 6; ++ks) {
        const int kbyte = ks * 32;
        uint32_t ah[4][4], al[4][4], bhf[4][2], blf[4][2];
#pragma unroll
        for (int i = 0; i < 4; ++i) {
            int row = wm * 64 + i * 16 + a_row;
            uint32_t ad = sb + row * 208 + kbyte + a_hi;
            ldsm4(ah[i], C1_AH + ad);
            ldsm4(al[i], C1_AL + ad);
        }
#pragma unroll
        for (int jp = 0; jp < 2; ++jp) {
            int row = wn * 32 + jp * 16 + b_row;
            uint32_t bd = sb + row * 208 + kbyte + b_hi;
            uint32_t t0[4], t1[4];
            ldsm4(t0, C1_BH + bd);
            ldsm4(t1, C1_BL + bd);
            bhf[jp*2][0] = t0[0]; bhf[jp*2][1] = t0[1];
            bhf[jp*2+1][0] = t0[2]; bhf[jp*2+1][1] = t0[3];
            blf[jp*2][0] = t1[0]; blf[jp*2][1] = t1[1];
            blf[jp*2+1][0] = t1[2]; blf[jp*2+1][1] = t1[3];
        }
#pragma unroll
        for (int i = 0; i < 4; ++i)
#pragma unroll
            for (int j = 0; j < 4; ++j) {
                mma16816(acc[i][j], ah[i], bhf[j]);
                mma16816(acc[i][j], ah[i], blf[j]);
                mma16816(acc[i][j], al[i], bhf[j]);
            }
    }
    __syncthreads();

    uint32_t* s_out = (uint32_t*)(smem + C1_AH);
    const int gq = lane >> 2, tig = lane & 3;
#pragma unroll
    for (int i = 0; i < 4; ++i) {
        int mloc = wm * 64 + i * 16 + gq;
        float b1a = __ldg(b1 + m0 + mloc), b1b = __ldg(b1 + m0 + mloc + 8);
#pragma unroll
        for (int j = 0; j < 4; ++j) {
            int nloc = wn * 32 + j * 8 + tig * 2;
            uint32_t o0, o1;
            pack_hl2(fmaxf(acc[i][j][0] + b1a, 0.f), fmaxf(acc[i][j][1] + b1a, 0.f), o0, o1);
            s_out[nloc * 128 + mloc]       = o0;
            s_out[(nloc + 1) * 128 + mloc] = o1;
            pack_hl2(fmaxf(acc[i][j][2] + b1b, 0.f), fmaxf(acc[i][j][3] + b1b, 0.f), o0, o1);
            s_out[nloc * 128 + mloc + 8]       = o0;
            s_out[(nloc + 1) * 128 + mloc + 8] = o1;
        }
    }
    __syncthreads();
#pragma unroll
    for (int t = 0; t < 8; ++t) {
        int f = tid + t * 256;
        int nloc = f >> 4, seg = f & 15;
        uint4 p0 = *(uint4*)(s_out + nloc * 128 + seg * 8);
        uint4 p1 = *(uint4*)(s_out + nloc * 128 + seg * 8 + 4);
        uint4 hq, lq;
        hq.x = (p0.x & 0xFFFFu) | (p0.y << 16);
        hq.y = (p0.z & 0xFFFFu) | (p0.w << 16);
        hq.z = (p1.x & 0xFFFFu) | (p1.y << 16);
        hq.w = (p1.z & 0xFFFFu) | (p1.w << 16);
        lq.x = (p0.x >> 16) | (p0.y & 0xFFFF0000u);
        lq.y = (p0.z >> 16) | (p0.w & 0xFFFF0000u);
        lq.z = (p1.x >> 16) | (p1.y & 0xFFFF0000u);
        lq.w = (p1.z >> 16) | (p1.w & 0xFFFF0000u);
        size_t dst = (size_t)(n0 + nloc) * 256 + m0 + seg * 8;
        *(uint4*)(g_x1h + dst) = hq;
        *(uint4*)(g_x1l + dst) = lq;
    }
}

// ================= conv2: frozen best config =================
#define STAGE_BYTES 65536
#define AH_OFF 0
#define AL_OFF 16384
#define BH_OFF 32768
#define BL_OFF 49152

#define LOADF(S, TB, KB) do { \
    _Pragma("unroll") \
    for (int i = 0; i < 4; ++i) { \
        int row = wm * 64 + i * 16 + a_row; \
        uint32_t ad = (TB) + swz(row * 128 + (KB) + a_hi); \
        ldsm4(ah##S[i], AH_OFF + ad); \
        ldsm4(al##S[i], AL_OFF + ad); \
    } \
    _Pragma("unroll") \
    for (int jp = 0; jp < 2; ++jp) { \
        int row = wn * 32 + jp * 16 + b_row; \
        uint32_t bd = (TB) + swz(row * 128 + (KB) + b_hi); \
        uint32_t t0[4], t1[4]; \
        ldsm4(t0, BH_OFF + bd); \
        ldsm4(t1, BL_OFF + bd); \
        bh##S[jp*2][0] = t0[0]; bh##S[jp*2][1] = t0[1]; \
        bh##S[jp*2+1][0] = t0[2]; bh##S[jp*2+1][1] = t0[3]; \
        bl##S[jp*2][0] = t1[0]; bl##S[jp*2][1] = t1[1]; \
        bl##S[jp*2+1][0] = t1[2]; bl##S[jp*2+1][1] = t1[3]; \
    } \
} while (0)

#define MMAF(S) do { \
    _Pragma("unroll") \
    for (int i = 0; i < 4; ++i) \
        _Pragma("unroll") \
        for (int j = 0; j < 4; ++j) { \
            mma16816(acc[i][j], ah##S[i], bh##S[j]); \
            mma16816(acc[i][j], ah##S[i], bl##S[j]); \
            mma16816(acc[i][j], al##S[i], bh##S[j]); \
        } \
} while (0)

__global__ __launch_bounds__(256, 1) void conv2_mma_kernel() {
    extern __shared__ char smem[];
    const uint32_t sb = smem_u32(smem) + 1024;
    int* base_n = (int*)smem;
    const int tid = threadIdx.x;
    const int wid = tid >> 5, lane = tid & 31;
    const int m0 = blockIdx.y * 128;
    const int n0 = blockIdx.x * 128;
    const int wm = wid & 1, wn = wid >> 1;

    if (tid < 128) {
        int n = n0 + tid;
        int b = n / 36, s = n - b * 36;
        int oh = s / 6, ow = s - oh * 6;
        base_n[tid] = b * 102400 + (oh * 40 + ow * 2) * 256;
    }
    __syncthreads();

    const int e_m = tid >> 3, e_seg = tid & 7;
    const int a_row = lane & 15, a_hi = (lane >> 4) << 4;
    const int b_row = ((lane >> 4) << 3) + (lane & 7), b_hi = ((lane >> 3) & 1) << 4;

    auto preload = [&](int cc) {
        const uint32_t tb = sb + (cc % 3) * STAGE_BYTES;
        const int khw = cc >> 2, icq = cc & 3;
        const int kh = khw / 9, kw = khw - kh * 9;
        const int boff = (kh * 20 + kw) * 256 + icq * 64;
#pragma unroll
        for (int p = 0; p < 4; ++p) {
            int row = e_m + p * 32;
            int sw = swz(row * 128 + e_seg * 16);
            size_t asrc = (size_t)(m0 + row) * KGEMM + cc * 64 + e_seg * 8;
            cpasync16(tb + AH_OFF + sw, g_w2h + asrc);
            cpasync16(tb + AL_OFF + sw, g_w2l + asrc);
            size_t bsrc = (size_t)base_n[row] + boff + e_seg * 8;
            cpasync16(tb + BH_OFF + sw, g_x1h + bsrc);
            cpasync16(tb + BL_OFF + sw, g_x1l + bsrc);
        }
        CP_COMMIT();
    };

    float acc[4][4][4];
#pragma unroll
    for (int i = 0; i < 4; ++i)
#pragma unroll
        for (int j = 0; j < 4; ++j)
#pragma unroll
            for (int r = 0; r < 4; ++r) acc[i][j][r] = 0.f;

    uint32_t ahA[4][4], alA[4][4], bhA[4][2], blA[4][2];
    uint32_t ahB[4][4], alB[4][4], bhB[4][2], blB[4][2];

    preload(0);
    preload(1);

    for (int c = 0; c < NCHUNK; ++c) {
        if (c + 2 < NCHUNK) { CP_WAIT(1); } else { CP_WAIT(0); }
        __syncthreads();
        if (c + 2 < NCHUNK) preload(c + 2);

        const uint32_t tb = sb + (c % 3) * STAGE_BYTES;
        LOADF(A, tb, 0);
        LOADF(B, tb, 32);
        MMAF(A);
        LOADF(A, tb, 64);
        MMAF(B);
        LOADF(B, tb, 96);
        MMAF(A);
        MMAF(B);
    }
    __syncthreads();

    float* s_y = (float*)(smem + 1024);
    const int gq = lane >> 2, tig = lane & 3;
#pragma unroll
    for (int i = 0; i < 4; ++i) {
        int mloc = wm * 64 + i * 16 + gq;
#pragma unroll
        for (int j = 0; j < 4; ++j) {
            int nloc = wn * 32 + j * 8 + tig * 2;
            s_y[nloc * 128 + mloc]           = acc[i][j][0];
            s_y[(nloc + 1) * 128 + mloc]     = acc[i][j][1];
            s_y[nloc * 128 + mloc + 8]       = acc[i][j][2];
            s_y[(nloc + 1) * 128 + mloc + 8] = acc[i][j][3];
        }
    }
    __syncthreads();
#pragma unroll
    for (int t = 0; t < 16; ++t) {
        int f = tid + t * 256;
        int nloc = f >> 5, seg = f & 31;
        float4 v = *(float4*)(s_y + nloc * 128 + seg * 4);
        *(float4*)(g_y2 + (size_t)(n0 + nloc) * 256 + m0 + seg * 4) = v;
    }
}

// ================= fused: squash + caps_up + routing, 2 rounds per block =================
#define FR_WT   0                    // half[46080]  92160B
#define FR_UP   92160                // half[8*5760] 92160B
#define FR_U    184320               // float[8*288]  9216B
#define FR_PW   193536               // per-warp float[896]*8 = 28672B
#define FR_SMEM 222208

__global__ __launch_bounds__(256, 1) void fused_route_kernel(const float* __restrict__ b_route,
                                                             const float* __restrict__ b2) {
    extern __shared__ char sm[];
    __half* sWt = (__half*)(sm + FR_WT);
    __half* sUp = (__half*)(sm + FR_UP);
    float*  sU  = (float*)(sm + FR_U);
    const int tid = threadIdx.x;
    const int wid = tid >> 5, lane = tid & 31;
    const int g  = blockIdx.x >> 4;      // 32 g x 16 bt
    const int bt = blockIdx.x & 15;

    // stage Wt once (5760 uint4 = 92160B)
    {
        const uint4* src = (const uint4*)(g_wth + (size_t)g * 46080);
        uint4* dst = (uint4*)sWt;
        for (int f = tid; f < 5760; f += 256) dst[f] = src[f];
    }
    float b2v[8];
#pragma unroll
    for (int i = 0; i < 8; ++i) b2v[i] = __ldg(&b2[g * 8 + i]);

    // b_route staged once per warp into registers (reused both rounds)
    float br_reg[12];
    {
        const float* src = b_route + g * 360;
#pragma unroll
        for (int r = 0; r < 12; ++r) {
            int e = lane + 32 * r;
            br_reg[r] = (e < 360) ? __ldg(src + e) : 0.f;
        }
    }

    for (int rb = 0; rb < 2; ++rb) {
        const int bimg = (bt * 2 + rb) * 8 + wid;

        // squash -> sU
#pragma unroll
        for (int r = 0; r < 2; ++r) {
            int s = lane + 32 * r;
            if (s < 36) {
                const float* y = g_y2 + (size_t)(bimg * 36 + s) * 256 + g * 8;
                float4 y0 = *(const float4*)y;
                float4 y1 = *(const float4*)(y + 4);
                float u0 = y0.x + b2v[0], u1 = y0.y + b2v[1], u2 = y0.z + b2v[2], u3 = y0.w + b2v[3];
                float u4 = y1.x + b2v[4], u5 = y1.y + b2v[5], u6 = y1.z + b2v[6], u7 = y1.w + b2v[7];
                float l2 = u0*u0+u1*u1+u2*u2+u3*u3+u4*u4+u5*u5+u6*u6+u7*u7;
                float sc = l2 / ((1.f + l2) * (sqrtf(l2) + 1e-8f));
                *(float4*)(sU + wid * 288 + s * 8)     = make_float4(u0*sc, u1*sc, u2*sc, u3*sc);
                *(float4*)(sU + wid * 288 + s * 8 + 4) = make_float4(u4*sc, u5*sc, u6*sc, u7*sc);
            }
        }
        __syncthreads();   // sU visible (also: round 0 Wt staged; round 1 all warps past prior routing)

        // up[img][s][j]
        for (int img = 0; img < 8; ++img) {
            const float* uu = sU + img * 288;
            __half* upd = sUp + img * 5760;
            for (int f = tid; f < 2880; f += 256) {
                int s = f / 80, jp = f - s * 80;
                float4 ua = *(const float4*)(uu + s * 8);
                float4 ub = *(const float4*)(uu + s * 8 + 4);
                const __half* w0 = sWt + (s * 160 + jp * 2) * 8;
                float d0 = dot8h(ua, ub, w0);
                float d1 = dot8h(ua, ub, w0 + 8);
                *(__half2*)(upd + f * 2) = __floats2half2_rn(d0, d1);
            }
        }
        __syncthreads();

        // routing (warp-per-image)
        const __half* upw = sUp + wid * 5760;
        float* bb  = (float*)(sm + FR_PW) + wid * 896;
        float* cc  = bb + 360;
        float* vv  = cc + 360;
        float* nrm = vv + 160;

#pragma unroll
        for (int r = 0; r < 12; ++r) {
            int e = lane + 32 * r;
            if (e < 360) bb[e] = br_reg[r];
        }
        __syncwarp();

        float sv[5];
        for (int it = 0; it < 3; ++it) {
#pragma unroll
            for (int r = 0; r < 2; ++r) {
                int s = lane + 32 * r;
                if (s < 36) {
                    float mx = -1e30f;
#pragma unroll
                    for (int o = 0; o < OC; ++o) mx = fmaxf(mx, bb[s * 10 + o]);
                    float e[OC]; float sum = 0.f;
#pragma unroll
                    for (int o = 0; o < OC; ++o) { e[o] = expf(bb[s * 10 + o] - mx); sum += e[o]; }
                    float inv = 1.f / sum;
#pragma unroll
                    for (int o = 0; o < OC; ++o) cc[s * 10 + o] = e[o] * inv;
                }
            }
            __syncwarp();
#pragma unroll
            for (int q = 0; q < 5; ++q) {
                int od = lane + 32 * q;
                int o = od >> 4;
                float a = 0.f;
                for (int s = 0; s < 36; ++s)
                    a = fmaf(cc[s * 10 + o], __half2float(upw[s * 160 + od]), a);
                sv[q] = a;
                vv[od] = a;
            }
            __syncwarp();
            if (lane < OC) {
                float l2 = 0.f;
#pragma unroll
                for (int d = 0; d < OD; ++d) { float x = vv[lane * 16 + d]; l2 += x * x; }
                nrm[lane] = l2 / ((1.f + l2) * (sqrtf(l2) + 1e-8f));
            }
            __syncwarp();
#pragma unroll
            for (int q = 0; q < 5; ++q) {
                int od = lane + 32 * q;
                vv[od] = sv[q] * nrm[od >> 4];
            }
            __syncwarp();
            if (it < 2) {
#pragma unroll
                for (int r = 0; r < 12; ++r) {
                    int e = lane + 32 * r;
                    if (e < 360) {
                        int s = e / 10, o = e - s * 10;
                        const __half2* u2 = (const __half2*)(upw + s * 160 + o * 16);
                        float a = 0.f;
#pragma unroll
                        for (int d2 = 0; d2 < 8; ++d2) {
                            float2 uf = __half22float2(u2[d2]);
                            a = fmaf(uf.x, vv[o * 16 + d2 * 2], a);
                            a = fmaf(uf.y, vv[o * 16 + d2 * 2 + 1], a);
                        }
                        bb[e] += a;
                    }
                }
                __syncwarp();
            }
        }
        float* dst = g_vg + (size_t)(bimg * G_NUM + g) * 160;
#pragma unroll
        for (int q = 0; q < 5; ++q) dst[lane + 32 * q] = vv[lane + 32 * q];
    }
}

// ================= finalize =================
__global__ void finalize_kernel(float* __restrict__ out) {
    __shared__ float sv[OC * OD];
    const int b = blockIdx.x;
    const int tid = threadIdx.x;
    float a = 0.f;
    for (int g = 0; g < G_NUM; ++g)
        a += g_vg[(size_t)(b * G_NUM + g) * 160 + tid];
    out[b * 160 + tid] = a;
    sv[tid] = a;
    __syncthreads();
    if (tid < OC) {
        float l2 = 0.f;
#pragma unroll
        for (int d = 0; d < OD; ++d) { float x = sv[tid * 16 + d]; l2 += x * x; }
        out[B_SZ * 160 + b * OC + tid] = sqrtf(l2);
    }
}

// ================= launch =================
extern "C" void kernel_launch(void* const* d_in, const int* in_sizes, int n_in,
                              void* d_out, int out_size) {
    const float* inp     = (const float*)d_in[0];
    const float* W1      = (const float*)d_in[1];
    const float* b1      = (const float*)d_in[2];
    const float* W2      = (const float*)d_in[3];
    const float* b2      = (const float*)d_in[4];
    const float* Wcaps   = (const float*)d_in[5];
    const float* b_route = (const float*)d_in[6];
    float* out = (float*)d_out;

    const int w2_smem    = 20736 * 4;
    const int conv2_smem = 1024 + 3 * STAGE_BYTES;   // 197632
    cudaFuncSetAttribute(w2_convert_kernel, cudaFuncAttributeMaxDynamicSharedMemorySize, w2_smem);
    cudaFuncSetAttribute(conv1_mma_kernel,  cudaFuncAttributeMaxDynamicSharedMemorySize, C1_SMEM);
    cudaFuncSetAttribute(conv2_mma_kernel,  cudaFuncAttributeMaxDynamicSharedMemorySize, conv2_smem);
    cudaFuncSetAttribute(fused_route_kernel, cudaFuncAttributeMaxDynamicSharedMemorySize, FR_SMEM);

    static cudaStream_t s2 = nullptr;
    static cudaEvent_t evFork = nullptr, evJoin = nullptr;
    if (s2 == nullptr) {
        cudaStreamCreateWithFlags(&s2, cudaStreamNonBlocking);
        cudaEventCreateWithFlags(&evFork, cudaEventDisableTiming);
        cudaEventCreateWithFlags(&evJoin, cudaEventDisableTiming);
    }

    cudaEventRecord(evFork, 0);
    cudaStreamWaitEvent(s2, evFork, 0);
    w2_convert_kernel<<<C1, 256, w2_smem, s2>>>(W2);
    prep_wt<<<G_NUM * GS, 256, 0, s2>>>(Wcaps);
    cudaEventRecord(evJoin, s2);

    prep_w1<<<(C1 * 96 + 255) / 256, 256>>>(W1);
    dim3 g1(N1 / 128, 2);            // (800, 2)
    conv1_mma_kernel<<<g1, 256, C1_SMEM>>>(inp, b1);

    cudaStreamWaitEvent(0, evJoin, 0);
    dim3 g2(NGEMM / 128, 2);         // (72, 2)
    conv2_mma_kernel<<<g2, 256, conv2_smem>>>();

    fused_route_kernel<<<G_NUM * 16, 256, FR_SMEM>>>(b_route, b2);
    finalize_kernel<<<B_SZ, 160>>>(out);
}

// round 15
// speedup vs baseline: 1.0086x; 1.0086x over previous
#include <cuda_runtime.h>
#include <cuda_bf16.h>
#include <cuda_fp16.h>
#include <math.h>
#include <stdint.h>

// ---------------- problem constants ----------------
#define B_SZ   256
#define C1     256
#define H1     20
#define C2     256
#define GS     36
#define G_NUM  32
#define PD     8
#define OC     10
#define OD     16
#define KGEMM  (256*81)     // 20736
#define NGEMM  (B_SZ*GS)    // 9216
#define NCHUNK (KGEMM/64)   // 324
#define N1     (B_SZ*400)   // 102400

// ---------------- scratch ----------------
__device__ __nv_bfloat16 g_x1h[(size_t)N1 * C1];
__device__ __nv_bfloat16 g_x1l[(size_t)N1 * C1];
__device__ __nv_bfloat16 g_w1h[(size_t)C1 * 96];
__device__ __nv_bfloat16 g_w1l[(size_t)C1 * 96];
__device__ __nv_bfloat16 g_w2h[(size_t)C1 * KGEMM];
__device__ __nv_bfloat16 g_w2l[(size_t)C1 * KGEMM];
__device__ float  g_y2[(size_t)NGEMM * C2];                 // [(b*36+s)][oc]
__device__ __half g_wth[(size_t)G_NUM * GS * 160 * 8];      // Wcaps^T fp16 [g][s][j][i]
__device__ float  g_vg[(size_t)B_SZ * G_NUM * OC * OD];

// ---------------- helpers ----------------
__device__ __forceinline__ uint32_t smem_u32(const void* p) {
    uint32_t a;
    asm("{ .reg .u64 t; cvta.to.shared.u64 t, %1; cvt.u32.u64 %0, t; }" : "=r"(a) : "l"(p));
    return a;
}
__device__ __forceinline__ void cpasync16(uint32_t dst, const void* src) {
    asm volatile("cp.async.cg.shared.global [%0], [%1], 16;" :: "r"(dst), "l"(src));
}
#define CP_COMMIT()  asm volatile("cp.async.commit_group;" ::: "memory")
#define CP_WAIT(N)   asm volatile("cp.async.wait_group " #N ";" ::: "memory")

__device__ __forceinline__ void ldsm4(uint32_t* r, uint32_t addr) {
    asm volatile("ldmatrix.sync.aligned.m8n8.x4.shared.b16 {%0,%1,%2,%3}, [%4];"
        : "=r"(r[0]), "=r"(r[1]), "=r"(r[2]), "=r"(r[3]) : "r"(addr));
}
__device__ __forceinline__ void mma16816(float* d, const uint32_t* a, const uint32_t* b) {
    asm volatile(
        "mma.sync.aligned.m16n8k16.row.col.f32.bf16.bf16.f32 "
        "{%0,%1,%2,%3}, {%4,%5,%6,%7}, {%8,%9}, {%0,%1,%2,%3};"
        : "+f"(d[0]), "+f"(d[1]), "+f"(d[2]), "+f"(d[3])
        : "r"(a[0]), "r"(a[1]), "r"(a[2]), "r"(a[3]), "r"(b[0]), "r"(b[1]));
}
__device__ __forceinline__ int swz(int byte) { return byte ^ ((byte >> 3) & 0x70); }
__device__ __forceinline__ void pack_hl2(float v0, float v1, uint32_t& o0, uint32_t& o1) {
    __nv_bfloat162 h2v = __floats2bfloat162_rn(v0, v1);
    uint32_t h2 = *(uint32_t*)&h2v;
    float f0 = __uint_as_float(h2 << 16);
    float f1 = __uint_as_float(h2 & 0xFFFF0000u);
    __nv_bfloat162 l2v = __floats2bfloat162_rn(v0 - f0, v1 - f1);
    uint32_t l2 = *(uint32_t*)&l2v;
    o0 = __byte_perm(h2, l2, 0x5410);
    o1 = __byte_perm(h2, l2, 0x7632);
}
__device__ __forceinline__ float dot8h(float4 ua, float4 ub, const __half* w) {
    const __half2* w2 = (const __half2*)w;
    float2 f0 = __half22float2(w2[0]);
    float2 f1 = __half22float2(w2[1]);
    float2 f2 = __half22float2(w2[2]);
    float2 f3 = __half22float2(w2[3]);
    return ua.x*f0.x + ua.y*f0.y + ua.z*f1.x + ua.w*f1.y
         + ub.x*f2.x + ub.y*f2.y + ub.z*f3.x + ub.w*f3.y;
}

// ================= prep: W1 -> bf16 hi/lo padded =================
__global__ void prep_w1(const float* __restrict__ W1) {
    int idx = blockIdx.x * 256 + threadIdx.x;
    if (idx >= C1 * 96) return;
    int oc = idx / 96, k = idx - oc * 96;
    float w = (k < 81) ? W1[oc * 81 + k] : 0.f;
    __nv_bfloat16 h = __float2bfloat16(w);
    g_w1h[idx] = h;
    g_w1l[idx] = __float2bfloat16(w - __bfloat162float(h));
}

// ================= prep: Wcaps -> fp16 transposed [g][s][j][i] =================
__global__ void prep_wt(const float* __restrict__ Wcaps) {
    __shared__ float t[1280];
    const int gs = blockIdx.x;
    const int tid = threadIdx.x;
    for (int f = tid; f < 1280; f += 256) t[f] = Wcaps[(size_t)gs * 1280 + f];
    __syncthreads();
    for (int ff = tid; ff < 640; ff += 256) {
        int f = ff * 2;
        int j = f >> 3, i = f & 7;
        __half2 h = __floats2half2_rn(t[i * 160 + j], t[(i + 1) * 160 + j]);
        *(__half2*)(g_wth + (size_t)gs * 1280 + f) = h;
    }
}

// ================= prep: W2 -> bf16 hi/lo, k' = khw*256+ic =================
__global__ void w2_convert_kernel(const float* __restrict__ W2) {
    extern __shared__ float sw[];
    const int m = blockIdx.x, tid = threadIdx.x;
    for (int i = tid; i < 20736; i += 256) sw[i] = W2[(size_t)m * 20736 + i];
    __syncthreads();
    for (int t = tid; t < 2592; t += 256) {
        int base = t * 8;
        int khw = base >> 8, ic0 = base & 255;
        float v[8];
#pragma unroll
        for (int q = 0; q < 8; ++q) v[q] = sw[(ic0 + q) * 81 + khw];
        uint32_t hp[4], lp[4];
#pragma unroll
        for (int q = 0; q < 4; ++q) {
            __nv_bfloat16 h0 = __float2bfloat16(v[2*q]);
            __nv_bfloat16 h1 = __float2bfloat16(v[2*q+1]);
            __nv_bfloat16 l0 = __float2bfloat16(v[2*q]   - __bfloat162float(h0));
            __nv_bfloat16 l1 = __float2bfloat16(v[2*q+1] - __bfloat162float(h1));
            hp[q] = (uint32_t)__bfloat16_as_ushort(h0) | ((uint32_t)__bfloat16_as_ushort(h1) << 16);
            lp[q] = (uint32_t)__bfloat16_as_ushort(l0) | ((uint32_t)__bfloat16_as_ushort(l1) << 16);
        }
        *(uint4*)(g_w2h + (size_t)m * 20736 + base) = make_uint4(hp[0], hp[1], hp[2], hp[3]);
        *(uint4*)(g_w2l + (size_t)m * 20736 + base) = make_uint4(lp[0], lp[1], lp[2], lp[3]);
    }
}

// ================= conv1: split-3 bf16 HMMA (static-offset B build) =================
#define C1_IMG   0
#define C1_BASEN 6272
#define C1_AH    7168
#define C1_AL    (C1_AH + 26624)
#define C1_BH    (C1_AL + 26624)
#define C1_BL    (C1_BH + 26624)
#define C1_SMEM  (C1_BL + 26624)     // 113664

__device__ __forceinline__ constexpr int c1_off(int k) {
    return (k < 81) ? (k / 9) * 28 + (k % 9) : -1;
}
template<int K0>
__device__ __forceinline__ void c1_bbuild(const float* s_img, int base,
                                          uint32_t* bh, uint32_t* bl) {
#pragma unroll
    for (int kk = 0; kk < 24; ++kk) {
        const int k = K0 + kk * 2;
        const int o0 = c1_off(k), o1 = c1_off(k + 1);
        float v0 = (o0 >= 0) ? s_img[base + o0] : 0.f;
        float v1 = (o1 >= 0) ? s_img[base + o1] : 0.f;
        __nv_bfloat162 h2v = __floats2bfloat162_rn(v0, v1);
        uint32_t h2 = *(uint32_t*)&h2v;
        float f0 = __uint_as_float(h2 << 16);
        float f1 = __uint_as_float(h2 & 0xFFFF0000u);
        __nv_bfloat162 l2v = __floats2bfloat162_rn(v0 - f0, v1 - f1);
        bh[kk] = h2;
        bl[kk] = *(uint32_t*)&l2v;
    }
}

__global__ __launch_bounds__(256, 2) void conv1_mma_kernel(const float* __restrict__ inp,
                                                           const float* __restrict__ b1) {
    extern __shared__ char smem[];
    float* s_img  = (float*)(smem + C1_IMG);
    int*   base_n = (int*)(smem + C1_BASEN);
    const uint32_t sb = smem_u32(smem);
    const int tid = threadIdx.x;
    const int wid = tid >> 5, lane = tid & 31;
    const int n0 = blockIdx.x * 128;
    const int m0 = blockIdx.y * 128;
    const int wm = wid & 1, wn = wid >> 1;
    const int bA = n0 / 400;

    for (int i = tid; i < 1568; i += 256) {
        int bimg = bA + (i >= 784);
        s_img[i] = (bimg < B_SZ) ? inp[bimg * 784 + (i % 784)] : 0.f;
    }
    if (tid < 128) {
        int n = n0 + tid;
        int b = n / 400, r = n - b * 400;
        int oh = r / 20, ow = r - oh * 20;
        base_n[tid] = (b - bA) * 784 + oh * 28 + ow;
    }

    for (int p = 0; p < 6; ++p) {
        int f = tid + p * 256;
        int row = f / 12, seg = f % 12;
        uint4 vh = *(const uint4*)(g_w1h + (size_t)(m0 + row) * 96 + seg * 8);
        uint4 vl = *(const uint4*)(g_w1l + (size_t)(m0 + row) * 96 + seg * 8);
        *(uint4*)(smem + C1_AH + row * 208 + seg * 16) = vh;
        *(uint4*)(smem + C1_AL + row * 208 + seg * 16) = vl;
    }
    __syncthreads();

    {
        const int row = tid >> 1;
        const int half = tid & 1;
        const int base = base_n[row];
        uint32_t* bh = (uint32_t*)(smem + C1_BH + row * 208) + half * 24;
        uint32_t* bl = (uint32_t*)(smem + C1_BL + row * 208) + half * 24;
        if (half == 0) c1_bbuild<0>(s_img, base, bh, bl);
        else           c1_bbuild<48>(s_img, base, bh, bl);
    }
    __syncthreads();

    const int a_row = lane & 15, a_hi = (lane >> 4) << 4;
    const int b_row = ((lane >> 4) << 3) + (lane & 7), b_hi = ((lane >> 3) & 1) << 4;

    float acc[4][4][4];
#pragma unroll
    for (int i = 0; i < 4; ++i)
#pragma unroll
        for (int j = 0; j < 4; ++j)
#pragma unroll
            for (int r = 0; r < 4; ++r) acc[i][j][r] = 0.f;

#pragma unroll
    for (int ks = 0; ks < 6; ++ks) {
        const int kbyte = ks * 32;
        uint32_t ah[4][4], al[4][4], bhf[4][2], blf[4][2];
#pragma unroll
        for (int i = 0; i < 4; ++i) {
            int row = wm * 64 + i * 16 + a_row;
            uint32_t ad = sb + row * 208 + kbyte + a_hi;
            ldsm4(ah[i], C1_AH + ad);
            ldsm4(al[i], C1_AL + ad);
        }
#pragma unroll
        for (int jp = 0; jp < 2; ++jp) {
            int row = wn * 32 + jp * 16 + b_row;
            uint32_t bd = sb + row * 208 + kbyte + b_hi;
            uint32_t t0[4], t1[4];
            ldsm4(t0, C1_BH + bd);
            ldsm4(t1, C1_BL + bd);
            bhf[jp*2][0] = t0[0]; bhf[jp*2][1] = t0[1];
            bhf[jp*2+1][0] = t0[2]; bhf[jp*2+1][1] = t0[3];
            blf[jp*2][0] = t1[0]; blf[jp*2][1] = t1[1];
            blf[jp*2+1][0] = t1[2]; blf[jp*2+1][1] = t1[3];
        }
#pragma unroll
        for (int i = 0; i < 4; ++i)
#pragma unroll
            for (int j = 0; j < 4; ++j) {
                mma16816(acc[i][j], ah[i], bhf[j]);
                mma16816(acc[i][j], ah[i], blf[j]);
                mma16816(acc[i][j], al[i], bhf[j]);
            }
    }
    __syncthreads();

    uint32_t* s_out = (uint32_t*)(smem + C1_AH);
    const int gq = lane >> 2, tig = lane & 3;
#pragma unroll
    for (int i = 0; i < 4; ++i) {
        int mloc = wm * 64 + i * 16 + gq;
        float b1a = __ldg(b1 + m0 + mloc), b1b = __ldg(b1 + m0 + mloc + 8);
#pragma unroll
        for (int j = 0; j < 4; ++j) {
            int nloc = wn * 32 + j * 8 + tig * 2;
            uint32_t o0, o1;
            pack_hl2(fmaxf(acc[i][j][0] + b1a, 0.f), fmaxf(acc[i][j][1] + b1a, 0.f), o0, o1);
            s_out[nloc * 128 + mloc]       = o0;
            s_out[(nloc + 1) * 128 + mloc] = o1;
            pack_hl2(fmaxf(acc[i][j][2] + b1b, 0.f), fmaxf(acc[i][j][3] + b1b, 0.f), o0, o1);
            s_out[nloc * 128 + mloc + 8]       = o0;
            s_out[(nloc + 1) * 128 + mloc + 8] = o1;
        }
    }
    __syncthreads();
#pragma unroll
    for (int t = 0; t < 8; ++t) {
        int f = tid + t * 256;
        int nloc = f >> 4, seg = f & 15;
        uint4 p0 = *(uint4*)(s_out + nloc * 128 + seg * 8);
        uint4 p1 = *(uint4*)(s_out + nloc * 128 + seg * 8 + 4);
        uint4 hq, lq;
        hq.x = (p0.x & 0xFFFFu) | (p0.y << 16);
        hq.y = (p0.z & 0xFFFFu) | (p0.w << 16);
        hq.z = (p1.x & 0xFFFFu) | (p1.y << 16);
        hq.w = (p1.z & 0xFFFFu) | (p1.w << 16);
        lq.x = (p0.x >> 16) | (p0.y & 0xFFFF0000u);
        lq.y = (p0.z >> 16) | (p0.w & 0xFFFF0000u);
        lq.z = (p1.x >> 16) | (p1.y & 0xFFFF0000u);
        lq.w = (p1.z >> 16) | (p1.w & 0xFFFF0000u);
        size_t dst = (size_t)(n0 + nloc) * 256 + m0 + seg * 8;
        *(uint4*)(g_x1h + dst) = hq;
        *(uint4*)(g_x1l + dst) = lq;
    }
}

// ================= conv2: frozen best config =================
#define STAGE_BYTES 65536
#define AH_OFF 0
#define AL_OFF 16384
#define BH_OFF 32768
#define BL_OFF 49152

#define LOADF(S, TB, KB) do { \
    _Pragma("unroll") \
    for (int i = 0; i < 4; ++i) { \
        int row = wm * 64 + i * 16 + a_row; \
        uint32_t ad = (TB) + swz(row * 128 + (KB) + a_hi); \
        ldsm4(ah##S[i], AH_OFF + ad); \
        ldsm4(al##S[i], AL_OFF + ad); \
    } \
    _Pragma("unroll") \
    for (int jp = 0; jp < 2; ++jp) { \
        int row = wn * 32 + jp * 16 + b_row; \
        uint32_t bd = (TB) + swz(row * 128 + (KB) + b_hi); \
        uint32_t t0[4], t1[4]; \
        ldsm4(t0, BH_OFF + bd); \
        ldsm4(t1, BL_OFF + bd); \
        bh##S[jp*2][0] = t0[0]; bh##S[jp*2][1] = t0[1]; \
        bh##S[jp*2+1][0] = t0[2]; bh##S[jp*2+1][1] = t0[3]; \
        bl##S[jp*2][0] = t1[0]; bl##S[jp*2][1] = t1[1]; \
        bl##S[jp*2+1][0] = t1[2]; bl##S[jp*2+1][1] = t1[3]; \
    } \
} while (0)

#define MMAF(S) do { \
    _Pragma("unroll") \
    for (int i = 0; i < 4; ++i) \
        _Pragma("unroll") \
        for (int j = 0; j < 4; ++j) { \
            mma16816(acc[i][j], ah##S[i], bh##S[j]); \
            mma16816(acc[i][j], ah##S[i], bl##S[j]); \
            mma16816(acc[i][j], al##S[i], bh##S[j]); \
        } \
} while (0)

__global__ __launch_bounds__(256, 1) void conv2_mma_kernel() {
    extern __shared__ char smem[];
    const uint32_t sb = smem_u32(smem) + 1024;
    int* base_n = (int*)smem;
    const int tid = threadIdx.x;
    const int wid = tid >> 5, lane = tid & 31;
    const int m0 = blockIdx.y * 128;
    const int n0 = blockIdx.x * 128;
    const int wm = wid & 1, wn = wid >> 1;

    if (tid < 128) {
        int n = n0 + tid;
        int b = n / 36, s = n - b * 36;
        int oh = s / 6, ow = s - oh * 6;
        base_n[tid] = b * 102400 + (oh * 40 + ow * 2) * 256;
    }
    __syncthreads();

    const int e_m = tid >> 3, e_seg = tid & 7;
    const int a_row = lane & 15, a_hi = (lane >> 4) << 4;
    const int b_row = ((lane >> 4) << 3) + (lane & 7), b_hi = ((lane >> 3) & 1) << 4;

    auto preload = [&](int cc) {
        const uint32_t tb = sb + (cc % 3) * STAGE_BYTES;
        const int khw = cc >> 2, icq = cc & 3;
        const int kh = khw / 9, kw = khw - kh * 9;
        const int boff = (kh * 20 + kw) * 256 + icq * 64;
#pragma unroll
        for (int p = 0; p < 4; ++p) {
            int row = e_m + p * 32;
            int sw = swz(row * 128 + e_seg * 16);
            size_t asrc = (size_t)(m0 + row) * KGEMM + cc * 64 + e_seg * 8;
            cpasync16(tb + AH_OFF + sw, g_w2h + asrc);
            cpasync16(tb + AL_OFF + sw, g_w2l + asrc);
            size_t bsrc = (size_t)base_n[row] + boff + e_seg * 8;
            cpasync16(tb + BH_OFF + sw, g_x1h + bsrc);
            cpasync16(tb + BL_OFF + sw, g_x1l + bsrc);
        }
        CP_COMMIT();
    };

    float acc[4][4][4];
#pragma unroll
    for (int i = 0; i < 4; ++i)
#pragma unroll
        for (int j = 0; j < 4; ++j)
#pragma unroll
            for (int r = 0; r < 4; ++r) acc[i][j][r] = 0.f;

    uint32_t ahA[4][4], alA[4][4], bhA[4][2], blA[4][2];
    uint32_t ahB[4][4], alB[4][4], bhB[4][2], blB[4][2];

    preload(0);
    preload(1);

    for (int c = 0; c < NCHUNK; ++c) {
        if (c + 2 < NCHUNK) { CP_WAIT(1); } else { CP_WAIT(0); }
        __syncthreads();
        if (c + 2 < NCHUNK) preload(c + 2);

        const uint32_t tb = sb + (c % 3) * STAGE_BYTES;
        LOADF(A, tb, 0);
        LOADF(B, tb, 32);
        MMAF(A);
        LOADF(A, tb, 64);
        MMAF(B);
        LOADF(B, tb, 96);
        MMAF(A);
        MMAF(B);
    }
    __syncthreads();

    float* s_y = (float*)(smem + 1024);
    const int gq = lane >> 2, tig = lane & 3;
#pragma unroll
    for (int i = 0; i < 4; ++i) {
        int mloc = wm * 64 + i * 16 + gq;
#pragma unroll
        for (int j = 0; j < 4; ++j) {
            int nloc = wn * 32 + j * 8 + tig * 2;
            s_y[nloc * 128 + mloc]           = acc[i][j][0];
            s_y[(nloc + 1) * 128 + mloc]     = acc[i][j][1];
            s_y[nloc * 128 + mloc + 8]       = acc[i][j][2];
            s_y[(nloc + 1) * 128 + mloc + 8] = acc[i][j][3];
        }
    }
    __syncthreads();
#pragma unroll
    for (int t = 0; t < 16; ++t) {
        int f = tid + t * 256;
        int nloc = f >> 5, seg = f & 31;
        float4 v = *(float4*)(s_y + nloc * 128 + seg * 4);
        *(float4*)(g_y2 + (size_t)(n0 + nloc) * 256 + m0 + seg * 4) = v;
    }
}

// ================= fused: squash + caps_up + routing (R13 single-round) =================
#define FR_WT   0                    // half[46080]  92160B
#define FR_UP   92160                // half[8*5760] 92160B
#define FR_U    184320               // float[8*288]  9216B
#define FR_PW   193536               // per-warp float[896]*8 = 28672B
#define FR_SMEM 222208

__global__ __launch_bounds__(256, 1) void fused_route_kernel(const float* __restrict__ b_route,
                                                             const float* __restrict__ b2) {
    extern __shared__ char sm[];
    __half* sWt = (__half*)(sm + FR_WT);
    __half* sUp = (__half*)(sm + FR_UP);
    float*  sU  = (float*)(sm + FR_U);
    const int tid = threadIdx.x;
    const int wid = tid >> 5, lane = tid & 31;
    const int g  = blockIdx.x >> 5;
    const int bt = blockIdx.x & 31;
    const int bimg = bt * 8 + wid;

    // 1. stage Wt (5760 uint4 = 92160B)
    {
        const uint4* src = (const uint4*)(g_wth + (size_t)g * 46080);
        uint4* dst = (uint4*)sWt;
        for (int f = tid; f < 5760; f += 256) dst[f] = src[f];
    }
    // 2. per-warp u = squash(y2 + b2)
    {
        float b2v[8];
#pragma unroll
        for (int i = 0; i < 8; ++i) b2v[i] = __ldg(&b2[g * 8 + i]);
#pragma unroll
        for (int r = 0; r < 2; ++r) {
            int s = lane + 32 * r;
            if (s < 36) {
                const float* y = g_y2 + (size_t)(bimg * 36 + s) * 256 + g * 8;
                float4 y0 = *(const float4*)y;
                float4 y1 = *(const float4*)(y + 4);
                float u0 = y0.x + b2v[0], u1 = y0.y + b2v[1], u2 = y0.z + b2v[2], u3 = y0.w + b2v[3];
                float u4 = y1.x + b2v[4], u5 = y1.y + b2v[5], u6 = y1.z + b2v[6], u7 = y1.w + b2v[7];
                float l2 = u0*u0+u1*u1+u2*u2+u3*u3+u4*u4+u5*u5+u6*u6+u7*u7;
                float sc = l2 / ((1.f + l2) * (sqrtf(l2) + 1e-8f));
                *(float4*)(sU + wid * 288 + s * 8)     = make_float4(u0*sc, u1*sc, u2*sc, u3*sc);
                *(float4*)(sU + wid * 288 + s * 8 + 4) = make_float4(u4*sc, u5*sc, u6*sc, u7*sc);
            }
        }
    }
    __syncthreads();

    // 3. up[img][s][j]
    for (int img = 0; img < 8; ++img) {
        const float* uu = sU + img * 288;
        __half* upd = sUp + img * 5760;
        for (int f = tid; f < 2880; f += 256) {
            int s = f / 80, jp = f - s * 80;
            float4 ua = *(const float4*)(uu + s * 8);
            float4 ub = *(const float4*)(uu + s * 8 + 4);
            const __half* w0 = sWt + (s * 160 + jp * 2) * 8;
            float d0 = dot8h(ua, ub, w0);
            float d1 = dot8h(ua, ub, w0 + 8);
            *(__half2*)(upd + f * 2) = __floats2half2_rn(d0, d1);
        }
    }
    __syncthreads();

    // 4. routing
    const __half* upw = sUp + wid * 5760;
    float* bb  = (float*)(sm + FR_PW) + wid * 896;
    float* cc  = bb + 360;
    float* vv  = cc + 360;
    float* nrm = vv + 160;

    {
        const float4* src = (const float4*)(b_route + g * 360);
#pragma unroll
        for (int r = 0; r < 3; ++r) {
            int f = lane + 32 * r;
            if (f < 90) ((float4*)bb)[f] = src[f];
        }
    }
    __syncwarp();

    float sv[5];
    for (int it = 0; it < 3; ++it) {
#pragma unroll
        for (int r = 0; r < 2; ++r) {
            int s = lane + 32 * r;
            if (s < 36) {
                float mx = -1e30f;
#pragma unroll
                for (int o = 0; o < OC; ++o) mx = fmaxf(mx, bb[s * 10 + o]);
                float e[OC]; float sum = 0.f;
#pragma unroll
                for (int o = 0; o < OC; ++o) { e[o] = expf(bb[s * 10 + o] - mx); sum += e[o]; }
                float inv = 1.f / sum;
#pragma unroll
                for (int o = 0; o < OC; ++o) cc[s * 10 + o] = e[o] * inv;
            }
        }
        __syncwarp();
#pragma unroll
        for (int q = 0; q < 5; ++q) {
            int od = lane + 32 * q;
            int o = od >> 4;
            float a = 0.f;
            for (int s = 0; s < 36; ++s)
                a = fmaf(cc[s * 10 + o], __half2float(upw[s * 160 + od]), a);
            sv[q] = a;
            vv[od] = a;
        }
        __syncwarp();
        if (lane < OC) {
            float l2 = 0.f;
#pragma unroll
            for (int d = 0; d < OD; ++d) { float x = vv[lane * 16 + d]; l2 += x * x; }
            nrm[lane] = l2 / ((1.f + l2) * (sqrtf(l2) + 1e-8f));
        }
        __syncwarp();
#pragma unroll
        for (int q = 0; q < 5; ++q) {
            int od = lane + 32 * q;
            vv[od] = sv[q] * nrm[od >> 4];
        }
        __syncwarp();
        if (it < 2) {
#pragma unroll
            for (int r = 0; r < 12; ++r) {
                int e = lane + 32 * r;
                if (e < 360) {
                    int s = e / 10, o = e - s * 10;
                    const __half2* u2 = (const __half2*)(upw + s * 160 + o * 16);
                    float a = 0.f;
#pragma unroll
                    for (int d2 = 0; d2 < 8; ++d2) {
                        float2 uf = __half22float2(u2[d2]);
                        a = fmaf(uf.x, vv[o * 16 + d2 * 2], a);
                        a = fmaf(uf.y, vv[o * 16 + d2 * 2 + 1], a);
                    }
                    bb[e] += a;
                }
            }
            __syncwarp();
        }
    }
    float* dst = g_vg + (size_t)(bimg * G_NUM + g) * 160;
#pragma unroll
    for (int q = 0; q < 5; ++q) dst[lane + 32 * q] = vv[lane + 32 * q];
}

// ================= finalize =================
__global__ void finalize_kernel(float* __restrict__ out) {
    __shared__ float sv[OC * OD];
    const int b = blockIdx.x;
    const int tid = threadIdx.x;
    float a = 0.f;
    for (int g = 0; g < G_NUM; ++g)
        a += g_vg[(size_t)(b * G_NUM + g) * 160 + tid];
    out[b * 160 + tid] = a;
    sv[tid] = a;
    __syncthreads();
    if (tid < OC) {
        float l2 = 0.f;
#pragma unroll
        for (int d = 0; d < OD; ++d) { float x = sv[tid * 16 + d]; l2 += x * x; }
        out[B_SZ * 160 + b * OC + tid] = sqrtf(l2);
    }
}

// ================= launch =================
extern "C" void kernel_launch(void* const* d_in, const int* in_sizes, int n_in,
                              void* d_out, int out_size) {
    const float* inp     = (const float*)d_in[0];
    const float* W1      = (const float*)d_in[1];
    const float* b1      = (const float*)d_in[2];
    const float* W2      = (const float*)d_in[3];
    const float* b2      = (const float*)d_in[4];
    const float* Wcaps   = (const float*)d_in[5];
    const float* b_route = (const float*)d_in[6];
    float* out = (float*)d_out;

    const int w2_smem    = 20736 * 4;
    const int conv2_smem = 1024 + 3 * STAGE_BYTES;   // 197632
    cudaFuncSetAttribute(w2_convert_kernel, cudaFuncAttributeMaxDynamicSharedMemorySize, w2_smem);
    cudaFuncSetAttribute(conv1_mma_kernel,  cudaFuncAttributeMaxDynamicSharedMemorySize, C1_SMEM);
    cudaFuncSetAttribute(conv2_mma_kernel,  cudaFuncAttributeMaxDynamicSharedMemorySize, conv2_smem);
    cudaFuncSetAttribute(fused_route_kernel, cudaFuncAttributeMaxDynamicSharedMemorySize, FR_SMEM);

    static cudaStream_t s2 = nullptr;
    static cudaEvent_t evFork = nullptr, evJoin = nullptr;
    if (s2 == nullptr) {
        cudaStreamCreateWithFlags(&s2, cudaStreamNonBlocking);
        cudaEventCreateWithFlags(&evFork, cudaEventDisableTiming);
        cudaEventCreateWithFlags(&evJoin, cudaEventDisableTiming);
    }

    cudaEventRecord(evFork, 0);
    cudaStreamWaitEvent(s2, evFork, 0);
    w2_convert_kernel<<<C1, 256, w2_smem, s2>>>(W2);
    prep_wt<<<G_NUM * GS, 256, 0, s2>>>(Wcaps);
    cudaEventRecord(evJoin, s2);

    prep_w1<<<(C1 * 96 + 255) / 256, 256>>>(W1);
    dim3 g1(N1 / 128, 2);            // (800, 2)
    conv1_mma_kernel<<<g1, 256, C1_SMEM>>>(inp, b1);

    cudaStreamWaitEvent(0, evJoin, 0);
    dim3 g2(NGEMM / 128, 2);         // (72, 2)
    conv2_mma_kernel<<<g2, 256, conv2_smem>>>();

    fused_route_kernel<<<G_NUM * 32, 256, FR_SMEM>>>(b_route, b2);
    finalize_kernel<<<B_SZ, 160>>>(out);
}

// round 16
// speedup vs baseline: 1.0117x; 1.0031x over previous
#include <cuda_runtime.h>
#include <cuda_bf16.h>
#include <cuda_fp16.h>
#include <math.h>
#include <stdint.h>

// ---------------- problem constants ----------------
#define B_SZ   256
#define C1     256
#define H1     20
#define C2     256
#define GS     36
#define G_NUM  32
#define PD     8
#define OC     10
#define OD     16
#define KGEMM  (256*81)     // 20736
#define NGEMM  (B_SZ*GS)    // 9216
#define NCHUNK (KGEMM/64)   // 324
#define N1     (B_SZ*400)   // 102400

// ---------------- scratch ----------------
__device__ __nv_bfloat16 g_x1h[(size_t)N1 * C1];
__device__ __nv_bfloat16 g_x1l[(size_t)N1 * C1];
__device__ __nv_bfloat16 g_w1h[(size_t)C1 * 96];
__device__ __nv_bfloat16 g_w1l[(size_t)C1 * 96];
__device__ __nv_bfloat16 g_w2h[(size_t)C1 * KGEMM];
__device__ __nv_bfloat16 g_w2l[(size_t)C1 * KGEMM];
__device__ float  g_y2[(size_t)NGEMM * C2];                 // [(b*36+s)][oc]
__device__ __half g_wth[(size_t)G_NUM * GS * 160 * 8];      // Wcaps^T fp16 [g][s][j][i]
__device__ float  g_vg[(size_t)B_SZ * G_NUM * OC * OD];

// ---------------- helpers ----------------
__device__ __forceinline__ uint32_t smem_u32(const void* p) {
    uint32_t a;
    asm("{ .reg .u64 t; cvta.to.shared.u64 t, %1; cvt.u32.u64 %0, t; }" : "=r"(a) : "l"(p));
    return a;
}
__device__ __forceinline__ void cpasync16(uint32_t dst, const void* src) {
    asm volatile("cp.async.cg.shared.global [%0], [%1], 16;" :: "r"(dst), "l"(src));
}
#define CP_COMMIT()  asm volatile("cp.async.commit_group;" ::: "memory")
#define CP_WAIT(N)   asm volatile("cp.async.wait_group " #N ";" ::: "memory")

__device__ __forceinline__ void ldsm4(uint32_t* r, uint32_t addr) {
    asm volatile("ldmatrix.sync.aligned.m8n8.x4.shared.b16 {%0,%1,%2,%3}, [%4];"
        : "=r"(r[0]), "=r"(r[1]), "=r"(r[2]), "=r"(r[3]) : "r"(addr));
}
__device__ __forceinline__ void mma16816(float* d, const uint32_t* a, const uint32_t* b) {
    asm volatile(
        "mma.sync.aligned.m16n8k16.row.col.f32.bf16.bf16.f32 "
        "{%0,%1,%2,%3}, {%4,%5,%6,%7}, {%8,%9}, {%0,%1,%2,%3};"
        : "+f"(d[0]), "+f"(d[1]), "+f"(d[2]), "+f"(d[3])
        : "r"(a[0]), "r"(a[1]), "r"(a[2]), "r"(a[3]), "r"(b[0]), "r"(b[1]));
}
__device__ __forceinline__ int swz(int byte) { return byte ^ ((byte >> 3) & 0x70); }
__device__ __forceinline__ void pack_hl2(float v0, float v1, uint32_t& o0, uint32_t& o1) {
    __nv_bfloat162 h2v = __floats2bfloat162_rn(v0, v1);
    uint32_t h2 = *(uint32_t*)&h2v;
    float f0 = __uint_as_float(h2 << 16);
    float f1 = __uint_as_float(h2 & 0xFFFF0000u);
    __nv_bfloat162 l2v = __floats2bfloat162_rn(v0 - f0, v1 - f1);
    uint32_t l2 = *(uint32_t*)&l2v;
    o0 = __byte_perm(h2, l2, 0x5410);
    o1 = __byte_perm(h2, l2, 0x7632);
}
__device__ __forceinline__ float dot8h(float4 ua, float4 ub, const __half* w) {
    const __half2* w2 = (const __half2*)w;
    float2 f0 = __half22float2(w2[0]);
    float2 f1 = __half22float2(w2[1]);
    float2 f2 = __half22float2(w2[2]);
    float2 f3 = __half22float2(w2[3]);
    return ua.x*f0.x + ua.y*f0.y + ua.z*f1.x + ua.w*f1.y
         + ub.x*f2.x + ub.y*f2.y + ub.z*f3.x + ub.w*f3.y;
}
// fast squash scale: l2 / ((1+l2)(sqrt(l2)+1e-8))
__device__ __forceinline__ float squash_scale(float l2) {
    return __fdividef(l2, (1.f + l2) * (__fsqrt_rn(l2) + 1e-8f));
}

// ================= prep: W1 -> bf16 hi/lo padded =================
__global__ void prep_w1(const float* __restrict__ W1) {
    int idx = blockIdx.x * 256 + threadIdx.x;
    if (idx >= C1 * 96) return;
    int oc = idx / 96, k = idx - oc * 96;
    float w = (k < 81) ? W1[oc * 81 + k] : 0.f;
    __nv_bfloat16 h = __float2bfloat16(w);
    g_w1h[idx] = h;
    g_w1l[idx] = __float2bfloat16(w - __bfloat162float(h));
}

// ================= prep: Wcaps -> fp16 transposed [g][s][j][i] =================
__global__ void prep_wt(const float* __restrict__ Wcaps) {
    __shared__ float t[1280];
    const int gs = blockIdx.x;
    const int tid = threadIdx.x;
    for (int f = tid; f < 1280; f += 256) t[f] = Wcaps[(size_t)gs * 1280 + f];
    __syncthreads();
    for (int ff = tid; ff < 640; ff += 256) {
        int f = ff * 2;
        int j = f >> 3, i = f & 7;
        __half2 h = __floats2half2_rn(t[i * 160 + j], t[(i + 1) * 160 + j]);
        *(__half2*)(g_wth + (size_t)gs * 1280 + f) = h;
    }
}

// ================= prep: W2 -> bf16 hi/lo, k' = khw*256+ic =================
__global__ void w2_convert_kernel(const float* __restrict__ W2) {
    extern __shared__ float sw[];
    const int m = blockIdx.x, tid = threadIdx.x;
    for (int i = tid; i < 20736; i += 256) sw[i] = W2[(size_t)m * 20736 + i];
    __syncthreads();
    for (int t = tid; t < 2592; t += 256) {
        int base = t * 8;
        int khw = base >> 8, ic0 = base & 255;
        float v[8];
#pragma unroll
        for (int q = 0; q < 8; ++q) v[q] = sw[(ic0 + q) * 81 + khw];
        uint32_t hp[4], lp[4];
#pragma unroll
        for (int q = 0; q < 4; ++q) {
            __nv_bfloat16 h0 = __float2bfloat16(v[2*q]);
            __nv_bfloat16 h1 = __float2bfloat16(v[2*q+1]);
            __nv_bfloat16 l0 = __float2bfloat16(v[2*q]   - __bfloat162float(h0));
            __nv_bfloat16 l1 = __float2bfloat16(v[2*q+1] - __bfloat162float(h1));
            hp[q] = (uint32_t)__bfloat16_as_ushort(h0) | ((uint32_t)__bfloat16_as_ushort(h1) << 16);
            lp[q] = (uint32_t)__bfloat16_as_ushort(l0) | ((uint32_t)__bfloat16_as_ushort(l1) << 16);
        }
        *(uint4*)(g_w2h + (size_t)m * 20736 + base) = make_uint4(hp[0], hp[1], hp[2], hp[3]);
        *(uint4*)(g_w2l + (size_t)m * 20736 + base) = make_uint4(lp[0], lp[1], lp[2], lp[3]);
    }
}

// ================= conv1: split-3 bf16 HMMA (static-offset B build) =================
#define C1_IMG   0
#define C1_BASEN 6272
#define C1_AH    7168
#define C1_AL    (C1_AH + 26624)
#define C1_BH    (C1_AL + 26624)
#define C1_BL    (C1_BH + 26624)
#define C1_SMEM  (C1_BL + 26624)     // 113664

__device__ __forceinline__ constexpr int c1_off(int k) {
    return (k < 81) ? (k / 9) * 28 + (k % 9) : -1;
}
template<int K0>
__device__ __forceinline__ void c1_bbuild(const float* s_img, int base,
                                          uint32_t* bh, uint32_t* bl) {
#pragma unroll
    for (int kk = 0; kk < 24; ++kk) {
        const int k = K0 + kk * 2;
        const int o0 = c1_off(k), o1 = c1_off(k + 1);
        float v0 = (o0 >= 0) ? s_img[base + o0] : 0.f;
        float v1 = (o1 >= 0) ? s_img[base + o1] : 0.f;
        __nv_bfloat162 h2v = __floats2bfloat162_rn(v0, v1);
        uint32_t h2 = *(uint32_t*)&h2v;
        float f0 = __uint_as_float(h2 << 16);
        float f1 = __uint_as_float(h2 & 0xFFFF0000u);
        __nv_bfloat162 l2v = __floats2bfloat162_rn(v0 - f0, v1 - f1);
        bh[kk] = h2;
        bl[kk] = *(uint32_t*)&l2v;
    }
}

__global__ __launch_bounds__(256, 2) void conv1_mma_kernel(const float* __restrict__ inp,
                                                           const float* __restrict__ b1) {
    extern __shared__ char smem[];
    float* s_img  = (float*)(smem + C1_IMG);
    int*   base_n = (int*)(smem + C1_BASEN);
    const uint32_t sb = smem_u32(smem);
    const int tid = threadIdx.x;
    const int wid = tid >> 5, lane = tid & 31;
    const int n0 = blockIdx.x * 128;
    const int m0 = blockIdx.y * 128;
    const int wm = wid & 1, wn = wid >> 1;
    const int bA = n0 / 400;

    for (int i = tid; i < 1568; i += 256) {
        int bimg = bA + (i >= 784);
        s_img[i] = (bimg < B_SZ) ? inp[bimg * 784 + (i % 784)] : 0.f;
    }
    if (tid < 128) {
        int n = n0 + tid;
        int b = n / 400, r = n - b * 400;
        int oh = r / 20, ow = r - oh * 20;
        base_n[tid] = (b - bA) * 784 + oh * 28 + ow;
    }

    for (int p = 0; p < 6; ++p) {
        int f = tid + p * 256;
        int row = f / 12, seg = f % 12;
        uint4 vh = *(const uint4*)(g_w1h + (size_t)(m0 + row) * 96 + seg * 8);
        uint4 vl = *(const uint4*)(g_w1l + (size_t)(m0 + row) * 96 + seg * 8);
        *(uint4*)(smem + C1_AH + row * 208 + seg * 16) = vh;
        *(uint4*)(smem + C1_AL + row * 208 + seg * 16) = vl;
    }
    __syncthreads();

    {
        const int row = tid >> 1;
        const int half = tid & 1;
        const int base = base_n[row];
        uint32_t* bh = (uint32_t*)(smem + C1_BH + row * 208) + half * 24;
        uint32_t* bl = (uint32_t*)(smem + C1_BL + row * 208) + half * 24;
        if (half == 0) c1_bbuild<0>(s_img, base, bh, bl);
        else           c1_bbuild<48>(s_img, base, bh, bl);
    }
    __syncthreads();

    const int a_row = lane & 15, a_hi = (lane >> 4) << 4;
    const int b_row = ((lane >> 4) << 3) + (lane & 7), b_hi = ((lane >> 3) & 1) << 4;

    float acc[4][4][4];
#pragma unroll
    for (int i = 0; i < 4; ++i)
#pragma unroll
        for (int j = 0; j < 4; ++j)
#pragma unroll
            for (int r = 0; r < 4; ++r) acc[i][j][r] = 0.f;

#pragma unroll
    for (int ks = 0; ks < 6; ++ks) {
        const int kbyte = ks * 32;
        uint32_t ah[4][4], al[4][4], bhf[4][2], blf[4][2];
#pragma unroll
        for (int i = 0; i < 4; ++i) {
            int row = wm * 64 + i * 16 + a_row;
            uint32_t ad = sb + row * 208 + kbyte + a_hi;
            ldsm4(ah[i], C1_AH + ad);
            ldsm4(al[i], C1_AL + ad);
        }
#pragma unroll
        for (int jp = 0; jp < 2; ++jp) {
            int row = wn * 32 + jp * 16 + b_row;
            uint32_t bd = sb + row * 208 + kbyte + b_hi;
            uint32_t t0[4], t1[4];
            ldsm4(t0, C1_BH + bd);
            ldsm4(t1, C1_BL + bd);
            bhf[jp*2][0] = t0[0]; bhf[jp*2][1] = t0[1];
            bhf[jp*2+1][0] = t0[2]; bhf[jp*2+1][1] = t0[3];
            blf[jp*2][0] = t1[0]; blf[jp*2][1] = t1[1];
            blf[jp*2+1][0] = t1[2]; blf[jp*2+1][1] = t1[3];
        }
#pragma unroll
        for (int i = 0; i < 4; ++i)
#pragma unroll
            for (int j = 0; j < 4; ++j) {
                mma16816(acc[i][j], ah[i], bhf[j]);
                mma16816(acc[i][j], ah[i], blf[j]);
                mma16816(acc[i][j], al[i], bhf[j]);
            }
    }
    __syncthreads();

    uint32_t* s_out = (uint32_t*)(smem + C1_AH);
    const int gq = lane >> 2, tig = lane & 3;
#pragma unroll
    for (int i = 0; i < 4; ++i) {
        int mloc = wm * 64 + i * 16 + gq;
        float b1a = __ldg(b1 + m0 + mloc), b1b = __ldg(b1 + m0 + mloc + 8);
#pragma unroll
        for (int j = 0; j < 4; ++j) {
            int nloc = wn * 32 + j * 8 + tig * 2;
            uint32_t o0, o1;
            pack_hl2(fmaxf(acc[i][j][0] + b1a, 0.f), fmaxf(acc[i][j][1] + b1a, 0.f), o0, o1);
            s_out[nloc * 128 + mloc]       = o0;
            s_out[(nloc + 1) * 128 + mloc] = o1;
            pack_hl2(fmaxf(acc[i][j][2] + b1b, 0.f), fmaxf(acc[i][j][3] + b1b, 0.f), o0, o1);
            s_out[nloc * 128 + mloc + 8]       = o0;
            s_out[(nloc + 1) * 128 + mloc + 8] = o1;
        }
    }
    __syncthreads();
#pragma unroll
    for (int t = 0; t < 8; ++t) {
        int f = tid + t * 256;
        int nloc = f >> 4, seg = f & 15;
        uint4 p0 = *(uint4*)(s_out + nloc * 128 + seg * 8);
        uint4 p1 = *(uint4*)(s_out + nloc * 128 + seg * 8 + 4);
        uint4 hq, lq;
        hq.x = (p0.x & 0xFFFFu) | (p0.y << 16);
        hq.y = (p0.z & 0xFFFFu) | (p0.w << 16);
        hq.z = (p1.x & 0xFFFFu) | (p1.y << 16);
        hq.w = (p1.z & 0xFFFFu) | (p1.w << 16);
        lq.x = (p0.x >> 16) | (p0.y & 0xFFFF0000u);
        lq.y = (p0.z >> 16) | (p0.w & 0xFFFF0000u);
        lq.z = (p1.x >> 16) | (p1.y & 0xFFFF0000u);
        lq.w = (p1.z >> 16) | (p1.w & 0xFFFF0000u);
        size_t dst = (size_t)(n0 + nloc) * 256 + m0 + seg * 8;
        *(uint4*)(g_x1h + dst) = hq;
        *(uint4*)(g_x1l + dst) = lq;
    }
}

// ================= conv2: frozen best config =================
#define STAGE_BYTES 65536
#define AH_OFF 0
#define AL_OFF 16384
#define BH_OFF 32768
#define BL_OFF 49152

#define LOADF(S, TB, KB) do { \
    _Pragma("unroll") \
    for (int i = 0; i < 4; ++i) { \
        int row = wm * 64 + i * 16 + a_row; \
        uint32_t ad = (TB) + swz(row * 128 + (KB) + a_hi); \
        ldsm4(ah##S[i], AH_OFF + ad); \
        ldsm4(al##S[i], AL_OFF + ad); \
    } \
    _Pragma("unroll") \
    for (int jp = 0; jp < 2; ++jp) { \
        int row = wn * 32 + jp * 16 + b_row; \
        uint32_t bd = (TB) + swz(row * 128 + (KB) + b_hi); \
        uint32_t t0[4], t1[4]; \
        ldsm4(t0, BH_OFF + bd); \
        ldsm4(t1, BL_OFF + bd); \
        bh##S[jp*2][0] = t0[0]; bh##S[jp*2][1] = t0[1]; \
        bh##S[jp*2+1][0] = t0[2]; bh##S[jp*2+1][1] = t0[3]; \
        bl##S[jp*2][0] = t1[0]; bl##S[jp*2][1] = t1[1]; \
        bl##S[jp*2+1][0] = t1[2]; bl##S[jp*2+1][1] = t1[3]; \
    } \
} while (0)

#define MMAF(S) do { \
    _Pragma("unroll") \
    for (int i = 0; i < 4; ++i) \
        _Pragma("unroll") \
        for (int j = 0; j < 4; ++j) { \
            mma16816(acc[i][j], ah##S[i], bh##S[j]); \
            mma16816(acc[i][j], ah##S[i], bl##S[j]); \
            mma16816(acc[i][j], al##S[i], bh##S[j]); \
        } \
} while (0)

__global__ __launch_bounds__(256, 1) void conv2_mma_kernel() {
    extern __shared__ char smem[];
    const uint32_t sb = smem_u32(smem) + 1024;
    int* base_n = (int*)smem;
    const int tid = threadIdx.x;
    const int wid = tid >> 5, lane = tid & 31;
    const int m0 = blockIdx.y * 128;
    const int n0 = blockIdx.x * 128;
    const int wm = wid & 1, wn = wid >> 1;

    if (tid < 128) {
        int n = n0 + tid;
        int b = n / 36, s = n - b * 36;
        int oh = s / 6, ow = s - oh * 6;
        base_n[tid] = b * 102400 + (oh * 40 + ow * 2) * 256;
    }
    __syncthreads();

    const int e_m = tid >> 3, e_seg = tid & 7;
    const int a_row = lane & 15, a_hi = (lane >> 4) << 4;
    const int b_row = ((lane >> 4) << 3) + (lane & 7), b_hi = ((lane >> 3) & 1) << 4;

    auto preload = [&](int cc) {
        const uint32_t tb = sb + (cc % 3) * STAGE_BYTES;
        const int khw = cc >> 2, icq = cc & 3;
        const int kh = khw / 9, kw = khw - kh * 9;
        const int boff = (kh * 20 + kw) * 256 + icq * 64;
#pragma unroll
        for (int p = 0; p < 4; ++p) {
            int row = e_m + p * 32;
            int sw = swz(row * 128 + e_seg * 16);
            size_t asrc = (size_t)(m0 + row) * KGEMM + cc * 64 + e_seg * 8;
            cpasync16(tb + AH_OFF + sw, g_w2h + asrc);
            cpasync16(tb + AL_OFF + sw, g_w2l + asrc);
            size_t bsrc = (size_t)base_n[row] + boff + e_seg * 8;
            cpasync16(tb + BH_OFF + sw, g_x1h + bsrc);
            cpasync16(tb + BL_OFF + sw, g_x1l + bsrc);
        }
        CP_COMMIT();
    };

    float acc[4][4][4];
#pragma unroll
    for (int i = 0; i < 4; ++i)
#pragma unroll
        for (int j = 0; j < 4; ++j)
#pragma unroll
            for (int r = 0; r < 4; ++r) acc[i][j][r] = 0.f;

    uint32_t ahA[4][4], alA[4][4], bhA[4][2], blA[4][2];
    uint32_t ahB[4][4], alB[4][4], bhB[4][2], blB[4][2];

    preload(0);
    preload(1);

    for (int c = 0; c < NCHUNK; ++c) {
        if (c + 2 < NCHUNK) { CP_WAIT(1); } else { CP_WAIT(0); }
        __syncthreads();
        if (c + 2 < NCHUNK) preload(c + 2);

        const uint32_t tb = sb + (c % 3) * STAGE_BYTES;
        LOADF(A, tb, 0);
        LOADF(B, tb, 32);
        MMAF(A);
        LOADF(A, tb, 64);
        MMAF(B);
        LOADF(B, tb, 96);
        MMAF(A);
        MMAF(B);
    }
    __syncthreads();

    float* s_y = (float*)(smem + 1024);
    const int gq = lane >> 2, tig = lane & 3;
#pragma unroll
    for (int i = 0; i < 4; ++i) {
        int mloc = wm * 64 + i * 16 + gq;
#pragma unroll
        for (int j = 0; j < 4; ++j) {
            int nloc = wn * 32 + j * 8 + tig * 2;
            s_y[nloc * 128 + mloc]           = acc[i][j][0];
            s_y[(nloc + 1) * 128 + mloc]     = acc[i][j][1];
            s_y[nloc * 128 + mloc + 8]       = acc[i][j][2];
            s_y[(nloc + 1) * 128 + mloc + 8] = acc[i][j][3];
        }
    }
    __syncthreads();
#pragma unroll
    for (int t = 0; t < 16; ++t) {
        int f = tid + t * 256;
        int nloc = f >> 5, seg = f & 31;
        float4 v = *(float4*)(s_y + nloc * 128 + seg * 4);
        *(float4*)(g_y2 + (size_t)(n0 + nloc) * 256 + m0 + seg * 4) = v;
    }
}

// ================= fused: squash + caps_up + routing (fast-math intrinsics) =================
#define FR_WT   0                    // half[46080]  92160B
#define FR_UP   92160                // half[8*5760] 92160B
#define FR_U    184320               // float[8*288]  9216B
#define FR_PW   193536               // per-warp float[896]*8 = 28672B
#define FR_SMEM 222208

__global__ __launch_bounds__(256, 1) void fused_route_kernel(const float* __restrict__ b_route,
                                                             const float* __restrict__ b2) {
    extern __shared__ char sm[];
    __half* sWt = (__half*)(sm + FR_WT);
    __half* sUp = (__half*)(sm + FR_UP);
    float*  sU  = (float*)(sm + FR_U);
    const int tid = threadIdx.x;
    const int wid = tid >> 5, lane = tid & 31;
    const int g  = blockIdx.x >> 5;
    const int bt = blockIdx.x & 31;
    const int bimg = bt * 8 + wid;

    // 1. stage Wt (5760 uint4 = 92160B)
    {
        const uint4* src = (const uint4*)(g_wth + (size_t)g * 46080);
        uint4* dst = (uint4*)sWt;
        for (int f = tid; f < 5760; f += 256) dst[f] = src[f];
    }
    // 2. per-warp u = squash(y2 + b2)
    {
        float b2v[8];
#pragma unroll
        for (int i = 0; i < 8; ++i) b2v[i] = __ldg(&b2[g * 8 + i]);
#pragma unroll
        for (int r = 0; r < 2; ++r) {
            int s = lane + 32 * r;
            if (s < 36) {
                const float* y = g_y2 + (size_t)(bimg * 36 + s) * 256 + g * 8;
                float4 y0 = *(const float4*)y;
                float4 y1 = *(const float4*)(y + 4);
                float u0 = y0.x + b2v[0], u1 = y0.y + b2v[1], u2 = y0.z + b2v[2], u3 = y0.w + b2v[3];
                float u4 = y1.x + b2v[4], u5 = y1.y + b2v[5], u6 = y1.z + b2v[6], u7 = y1.w + b2v[7];
                float l2 = u0*u0+u1*u1+u2*u2+u3*u3+u4*u4+u5*u5+u6*u6+u7*u7;
                float sc = squash_scale(l2);
                *(float4*)(sU + wid * 288 + s * 8)     = make_float4(u0*sc, u1*sc, u2*sc, u3*sc);
                *(float4*)(sU + wid * 288 + s * 8 + 4) = make_float4(u4*sc, u5*sc, u6*sc, u7*sc);
            }
        }
    }
    __syncthreads();

    // 3. up[img][s][j]
    for (int img = 0; img < 8; ++img) {
        const float* uu = sU + img * 288;
        __half* upd = sUp + img * 5760;
        for (int f = tid; f < 2880; f += 256) {
            int s = f / 80, jp = f - s * 80;
            float4 ua = *(const float4*)(uu + s * 8);
            float4 ub = *(const float4*)(uu + s * 8 + 4);
            const __half* w0 = sWt + (s * 160 + jp * 2) * 8;
            float d0 = dot8h(ua, ub, w0);
            float d1 = dot8h(ua, ub, w0 + 8);
            *(__half2*)(upd + f * 2) = __floats2half2_rn(d0, d1);
        }
    }
    __syncthreads();

    // 4. routing
    const __half* upw = sUp + wid * 5760;
    float* bb  = (float*)(sm + FR_PW) + wid * 896;
    float* cc  = bb + 360;
    float* vv  = cc + 360;
    float* nrm = vv + 160;

    {
        const float4* src = (const float4*)(b_route + g * 360);
#pragma unroll
        for (int r = 0; r < 3; ++r) {
            int f = lane + 32 * r;
            if (f < 90) ((float4*)bb)[f] = src[f];
        }
    }
    __syncwarp();

    float sv[5];
    for (int it = 0; it < 3; ++it) {
#pragma unroll
        for (int r = 0; r < 2; ++r) {
            int s = lane + 32 * r;
            if (s < 36) {
                float mx = -1e30f;
#pragma unroll
                for (int o = 0; o < OC; ++o) mx = fmaxf(mx, bb[s * 10 + o]);
                float e[OC]; float sum = 0.f;
#pragma unroll
                for (int o = 0; o < OC; ++o) { e[o] = __expf(bb[s * 10 + o] - mx); sum += e[o]; }
                float inv = __fdividef(1.f, sum);
#pragma unroll
                for (int o = 0; o < OC; ++o) cc[s * 10 + o] = e[o] * inv;
            }
        }
        __syncwarp();
#pragma unroll
        for (int q = 0; q < 5; ++q) {
            int od = lane + 32 * q;
            int o = od >> 4;
            float a = 0.f;
            for (int s = 0; s < 36; ++s)
                a = fmaf(cc[s * 10 + o], __half2float(upw[s * 160 + od]), a);
            sv[q] = a;
            vv[od] = a;
        }
        __syncwarp();
        if (lane < OC) {
            float l2 = 0.f;
#pragma unroll
            for (int d = 0; d < OD; ++d) { float x = vv[lane * 16 + d]; l2 += x * x; }
            nrm[lane] = squash_scale(l2);
        }
        __syncwarp();
#pragma unroll
        for (int q = 0; q < 5; ++q) {
            int od = lane + 32 * q;
            vv[od] = sv[q] * nrm[od >> 4];
        }
        __syncwarp();
        if (it < 2) {
#pragma unroll
            for (int r = 0; r < 12; ++r) {
                int e = lane + 32 * r;
                if (e < 360) {
                    int s = e / 10, o = e - s * 10;
                    const __half2* u2 = (const __half2*)(upw + s * 160 + o * 16);
                    float a = 0.f;
#pragma unroll
                    for (int d2 = 0; d2 < 8; ++d2) {
                        float2 uf = __half22float2(u2[d2]);
                        a = fmaf(uf.x, vv[o * 16 + d2 * 2], a);
                        a = fmaf(uf.y, vv[o * 16 + d2 * 2 + 1], a);
                    }
                    bb[e] += a;
                }
            }
            __syncwarp();
        }
    }
    float* dst = g_vg + (size_t)(bimg * G_NUM + g) * 160;
#pragma unroll
    for (int q = 0; q < 5; ++q) dst[lane + 32 * q] = vv[lane + 32 * q];
}

// ================= finalize =================
__global__ void finalize_kernel(float* __restrict__ out) {
    __shared__ float sv[OC * OD];
    const int b = blockIdx.x;
    const int tid = threadIdx.x;
    float a = 0.f;
    for (int g = 0; g < G_NUM; ++g)
        a += g_vg[(size_t)(b * G_NUM + g) * 160 + tid];
    out[b * 160 + tid] = a;
    sv[tid] = a;
    __syncthreads();
    if (tid < OC) {
        float l2 = 0.f;
#pragma unroll
        for (int d = 0; d < OD; ++d) { float x = sv[tid * 16 + d]; l2 += x * x; }
        out[B_SZ * 160 + b * OC + tid] = sqrtf(l2);
    }
}

// ================= launch =================
extern "C" void kernel_launch(void* const* d_in, const int* in_sizes, int n_in,
                              void* d_out, int out_size) {
    const float* inp     = (const float*)d_in[0];
    const float* W1      = (const float*)d_in[1];
    const float* b1      = (const float*)d_in[2];
    const float* W2      = (const float*)d_in[3];
    const float* b2      = (const float*)d_in[4];
    const float* Wcaps   = (const float*)d_in[5];
    const float* b_route = (const float*)d_in[6];
    float* out = (float*)d_out;

    const int w2_smem    = 20736 * 4;
    const int conv2_smem = 1024 + 3 * STAGE_BYTES;   // 197632
    cudaFuncSetAttribute(w2_convert_kernel, cudaFuncAttributeMaxDynamicSharedMemorySize, w2_smem);
    cudaFuncSetAttribute(conv1_mma_kernel,  cudaFuncAttributeMaxDynamicSharedMemorySize, C1_SMEM);
    cudaFuncSetAttribute(conv2_mma_kernel,  cudaFuncAttributeMaxDynamicSharedMemorySize, conv2_smem);
    cudaFuncSetAttribute(fused_route_kernel, cudaFuncAttributeMaxDynamicSharedMemorySize, FR_SMEM);

    static cudaStream_t s2 = nullptr;
    static cudaEvent_t evFork = nullptr, evJoin = nullptr;
    if (s2 == nullptr) {
        cudaStreamCreateWithFlags(&s2, cudaStreamNonBlocking);
        cudaEventCreateWithFlags(&evFork, cudaEventDisableTiming);
        cudaEventCreateWithFlags(&evJoin, cudaEventDisableTiming);
    }

    cudaEventRecord(evFork, 0);
    cudaStreamWaitEvent(s2, evFork, 0);
    w2_convert_kernel<<<C1, 256, w2_smem, s2>>>(W2);
    prep_wt<<<G_NUM * GS, 256, 0, s2>>>(Wcaps);
    cudaEventRecord(evJoin, s2);

    prep_w1<<<(C1 * 96 + 255) / 256, 256>>>(W1);
    dim3 g1(N1 / 128, 2);            // (800, 2)
    conv1_mma_kernel<<<g1, 256, C1_SMEM>>>(inp, b1);

    cudaStreamWaitEvent(0, evJoin, 0);
    dim3 g2(NGEMM / 128, 2);         // (72, 2)
    conv2_mma_kernel<<<g2, 256, conv2_smem>>>();

    fused_route_kernel<<<G_NUM * 32, 256, FR_SMEM>>>(b_route, b2);
    finalize_kernel<<<B_SZ, 160>>>(out);
}

// round 17
// speedup vs baseline: 1.0121x; 1.0004x over previous
#include <cuda_runtime.h>
#include <cuda_bf16.h>
#include <cuda_fp16.h>
#include <math.h>
#include <stdint.h>

// ---------------- problem constants ----------------
#define B_SZ   256
#define C1     256
#define H1     20
#define C2     256
#define GS     36
#define G_NUM  32
#define PD     8
#define OC     10
#define OD     16
#define KGEMM  (256*81)     // 20736
#define NGEMM  (B_SZ*GS)    // 9216
#define NCHUNK (KGEMM/64)   // 324
#define N1     (B_SZ*400)   // 102400

// ---------------- scratch ----------------
__device__ __nv_bfloat16 g_x1h[(size_t)N1 * C1];
__device__ __nv_bfloat16 g_x1l[(size_t)N1 * C1];
__device__ __nv_bfloat16 g_w1h[(size_t)C1 * 96];
__device__ __nv_bfloat16 g_w1l[(size_t)C1 * 96];
__device__ __nv_bfloat16 g_w2h[(size_t)C1 * KGEMM];
__device__ __nv_bfloat16 g_w2l[(size_t)C1 * KGEMM];
__device__ float  g_y2[(size_t)NGEMM * C2];                 // [(b*36+s)][oc]
__device__ __half g_wth[(size_t)G_NUM * GS * 160 * 8];      // Wcaps^T fp16 [g][s][j][i]
__device__ float  g_vg[(size_t)B_SZ * G_NUM * OC * OD];

// ---------------- helpers ----------------
__device__ __forceinline__ uint32_t smem_u32(const void* p) {
    uint32_t a;
    asm("{ .reg .u64 t; cvta.to.shared.u64 t, %1; cvt.u32.u64 %0, t; }" : "=r"(a) : "l"(p));
    return a;
}
__device__ __forceinline__ void cpasync16(uint32_t dst, const void* src) {
    asm volatile("cp.async.cg.shared.global [%0], [%1], 16;" :: "r"(dst), "l"(src));
}
#define CP_COMMIT()  asm volatile("cp.async.commit_group;" ::: "memory")
#define CP_WAIT(N)   asm volatile("cp.async.wait_group " #N ";" ::: "memory")

__device__ __forceinline__ void ldsm4(uint32_t* r, uint32_t addr) {
    asm volatile("ldmatrix.sync.aligned.m8n8.x4.shared.b16 {%0,%1,%2,%3}, [%4];"
        : "=r"(r[0]), "=r"(r[1]), "=r"(r[2]), "=r"(r[3]) : "r"(addr));
}
__device__ __forceinline__ void mma16816(float* d, const uint32_t* a, const uint32_t* b) {
    asm volatile(
        "mma.sync.aligned.m16n8k16.row.col.f32.bf16.bf16.f32 "
        "{%0,%1,%2,%3}, {%4,%5,%6,%7}, {%8,%9}, {%0,%1,%2,%3};"
        : "+f"(d[0]), "+f"(d[1]), "+f"(d[2]), "+f"(d[3])
        : "r"(a[0]), "r"(a[1]), "r"(a[2]), "r"(a[3]), "r"(b[0]), "r"(b[1]));
}
__device__ __forceinline__ int swz(int byte) { return byte ^ ((byte >> 3) & 0x70); }
__device__ __forceinline__ void pack_hl2(float v0, float v1, uint32_t& o0, uint32_t& o1) {
    __nv_bfloat162 h2v = __floats2bfloat162_rn(v0, v1);
    uint32_t h2 = *(uint32_t*)&h2v;
    float f0 = __uint_as_float(h2 << 16);
    float f1 = __uint_as_float(h2 & 0xFFFF0000u);
    __nv_bfloat162 l2v = __floats2bfloat162_rn(v0 - f0, v1 - f1);
    uint32_t l2 = *(uint32_t*)&l2v;
    o0 = __byte_perm(h2, l2, 0x5410);
    o1 = __byte_perm(h2, l2, 0x7632);
}
__device__ __forceinline__ float dot8h(float4 ua, float4 ub, const __half* w) {
    const __half2* w2 = (const __half2*)w;
    float2 f0 = __half22float2(w2[0]);
    float2 f1 = __half22float2(w2[1]);
    float2 f2 = __half22float2(w2[2]);
    float2 f3 = __half22float2(w2[3]);
    return ua.x*f0.x + ua.y*f0.y + ua.z*f1.x + ua.w*f1.y
         + ub.x*f2.x + ub.y*f2.y + ub.z*f3.x + ub.w*f3.y;
}
__device__ __forceinline__ float squash_scale(float l2) {
    return __fdividef(l2, (1.f + l2) * (__fsqrt_rn(l2) + 1e-8f));
}

// ================= prep: W1 -> bf16 hi/lo padded =================
__global__ void prep_w1(const float* __restrict__ W1) {
    int idx = blockIdx.x * 256 + threadIdx.x;
    if (idx >= C1 * 96) return;
    int oc = idx / 96, k = idx - oc * 96;
    float w = (k < 81) ? W1[oc * 81 + k] : 0.f;
    __nv_bfloat16 h = __float2bfloat16(w);
    g_w1h[idx] = h;
    g_w1l[idx] = __float2bfloat16(w - __bfloat162float(h));
}

// ================= prep: Wcaps -> fp16 transposed [g][s][j][i] =================
__global__ void prep_wt(const float* __restrict__ Wcaps) {
    __shared__ float t[1280];
    const int gs = blockIdx.x;
    const int tid = threadIdx.x;
    for (int f = tid; f < 1280; f += 256) t[f] = Wcaps[(size_t)gs * 1280 + f];
    __syncthreads();
    for (int ff = tid; ff < 640; ff += 256) {
        int f = ff * 2;
        int j = f >> 3, i = f & 7;
        __half2 h = __floats2half2_rn(t[i * 160 + j], t[(i + 1) * 160 + j]);
        *(__half2*)(g_wth + (size_t)gs * 1280 + f) = h;
    }
}

// ================= prep: W2 -> bf16 hi/lo, k' = khw*256+ic =================
__global__ void w2_convert_kernel(const float* __restrict__ W2) {
    extern __shared__ float sw[];
    const int m = blockIdx.x, tid = threadIdx.x;
    for (int i = tid; i < 20736; i += 256) sw[i] = W2[(size_t)m * 20736 + i];
    __syncthreads();
    for (int t = tid; t < 2592; t += 256) {
        int base = t * 8;
        int khw = base >> 8, ic0 = base & 255;
        float v[8];
#pragma unroll
        for (int q = 0; q < 8; ++q) v[q] = sw[(ic0 + q) * 81 + khw];
        uint32_t hp[4], lp[4];
#pragma unroll
        for (int q = 0; q < 4; ++q) {
            __nv_bfloat16 h0 = __float2bfloat16(v[2*q]);
            __nv_bfloat16 h1 = __float2bfloat16(v[2*q+1]);
            __nv_bfloat16 l0 = __float2bfloat16(v[2*q]   - __bfloat162float(h0));
            __nv_bfloat16 l1 = __float2bfloat16(v[2*q+1] - __bfloat162float(h1));
            hp[q] = (uint32_t)__bfloat16_as_ushort(h0) | ((uint32_t)__bfloat16_as_ushort(h1) << 16);
            lp[q] = (uint32_t)__bfloat16_as_ushort(l0) | ((uint32_t)__bfloat16_as_ushort(l1) << 16);
        }
        *(uint4*)(g_w2h + (size_t)m * 20736 + base) = make_uint4(hp[0], hp[1], hp[2], hp[3]);
        *(uint4*)(g_w2l + (size_t)m * 20736 + base) = make_uint4(lp[0], lp[1], lp[2], lp[3]);
    }
}

// ================= conv1: split-3 bf16 HMMA (static-offset B build) =================
#define C1_IMG   0
#define C1_BASEN 6272
#define C1_AH    7168
#define C1_AL    (C1_AH + 26624)
#define C1_BH    (C1_AL + 26624)
#define C1_BL    (C1_BH + 26624)
#define C1_SMEM  (C1_BL + 26624)     // 113664

__device__ __forceinline__ constexpr int c1_off(int k) {
    return (k < 81) ? (k / 9) * 28 + (k % 9) : -1;
}
template<int K0>
__device__ __forceinline__ void c1_bbuild(const float* s_img, int base,
                                          uint32_t* bh, uint32_t* bl) {
#pragma unroll
    for (int kk = 0; kk < 24; ++kk) {
        const int k = K0 + kk * 2;
        const int o0 = c1_off(k), o1 = c1_off(k + 1);
        float v0 = (o0 >= 0) ? s_img[base + o0] : 0.f;
        float v1 = (o1 >= 0) ? s_img[base + o1] : 0.f;
        __nv_bfloat162 h2v = __floats2bfloat162_rn(v0, v1);
        uint32_t h2 = *(uint32_t*)&h2v;
        float f0 = __uint_as_float(h2 << 16);
        float f1 = __uint_as_float(h2 & 0xFFFF0000u);
        __nv_bfloat162 l2v = __floats2bfloat162_rn(v0 - f0, v1 - f1);
        bh[kk] = h2;
        bl[kk] = *(uint32_t*)&l2v;
    }
}

__global__ __launch_bounds__(256, 2) void conv1_mma_kernel(const float* __restrict__ inp,
                                                           const float* __restrict__ b1) {
    extern __shared__ char smem[];
    float* s_img  = (float*)(smem + C1_IMG);
    int*   base_n = (int*)(smem + C1_BASEN);
    const uint32_t sb = smem_u32(smem);
    const int tid = threadIdx.x;
    const int wid = tid >> 5, lane = tid & 31;
    const int n0 = blockIdx.x * 128;
    const int m0 = blockIdx.y * 128;
    const int wm = wid & 1, wn = wid >> 1;
    const int bA = n0 / 400;

    for (int i = tid; i < 1568; i += 256) {
        int bimg = bA + (i >= 784);
        s_img[i] = (bimg < B_SZ) ? inp[bimg * 784 + (i % 784)] : 0.f;
    }
    if (tid < 128) {
        int n = n0 + tid;
        int b = n / 400, r = n - b * 400;
        int oh = r / 20, ow = r - oh * 20;
        base_n[tid] = (b - bA) * 784 + oh * 28 + ow;
    }

    for (int p = 0; p < 6; ++p) {
        int f = tid + p * 256;
        int row = f / 12, seg = f % 12;
        uint4 vh = *(const uint4*)(g_w1h + (size_t)(m0 + row) * 96 + seg * 8);
        uint4 vl = *(const uint4*)(g_w1l + (size_t)(m0 + row) * 96 + seg * 8);
        *(uint4*)(smem + C1_AH + row * 208 + seg * 16) = vh;
        *(uint4*)(smem + C1_AL + row * 208 + seg * 16) = vl;
    }
    __syncthreads();

    {
        const int row = tid >> 1;
        const int half = tid & 1;
        const int base = base_n[row];
        uint32_t* bh = (uint32_t*)(smem + C1_BH + row * 208) + half * 24;
        uint32_t* bl = (uint32_t*)(smem + C1_BL + row * 208) + half * 24;
        if (half == 0) c1_bbuild<0>(s_img, base, bh, bl);
        else           c1_bbuild<48>(s_img, base, bh, bl);
    }
    __syncthreads();

    const int a_row = lane & 15, a_hi = (lane >> 4) << 4;
    const int b_row = ((lane >> 4) << 3) + (lane & 7), b_hi = ((lane >> 3) & 1) << 4;

    float acc[4][4][4];
#pragma unroll
    for (int i = 0; i < 4; ++i)
#pragma unroll
        for (int j = 0; j < 4; ++j)
#pragma unroll
            for (int r = 0; r < 4; ++r) acc[i][j][r] = 0.f;

#pragma unroll
    for (int ks = 0; ks < 6; ++ks) {
        const int kbyte = ks * 32;
        uint32_t ah[4][4], al[4][4], bhf[4][2], blf[4][2];
#pragma unroll
        for (int i = 0; i < 4; ++i) {
            int row = wm * 64 + i * 16 + a_row;
            uint32_t ad = sb + row * 208 + kbyte + a_hi;
            ldsm4(ah[i], C1_AH + ad);
            ldsm4(al[i], C1_AL + ad);
        }
#pragma unroll
        for (int jp = 0; jp < 2; ++jp) {
            int row = wn * 32 + jp * 16 + b_row;
            uint32_t bd = sb + row * 208 + kbyte + b_hi;
            uint32_t t0[4], t1[4];
            ldsm4(t0, C1_BH + bd);
            ldsm4(t1, C1_BL + bd);
            bhf[jp*2][0] = t0[0]; bhf[jp*2][1] = t0[1];
            bhf[jp*2+1][0] = t0[2]; bhf[jp*2+1][1] = t0[3];
            blf[jp*2][0] = t1[0]; blf[jp*2][1] = t1[1];
            blf[jp*2+1][0] = t1[2]; blf[jp*2+1][1] = t1[3];
        }
#pragma unroll
        for (int i = 0; i < 4; ++i)
#pragma unroll
            for (int j = 0; j < 4; ++j) {
                mma16816(acc[i][j], ah[i], bhf[j]);
                mma16816(acc[i][j], ah[i], blf[j]);
                mma16816(acc[i][j], al[i], bhf[j]);
            }
    }
    __syncthreads();

    uint32_t* s_out = (uint32_t*)(smem + C1_AH);
    const int gq = lane >> 2, tig = lane & 3;
#pragma unroll
    for (int i = 0; i < 4; ++i) {
        int mloc = wm * 64 + i * 16 + gq;
        float b1a = __ldg(b1 + m0 + mloc), b1b = __ldg(b1 + m0 + mloc + 8);
#pragma unroll
        for (int j = 0; j < 4; ++j) {
            int nloc = wn * 32 + j * 8 + tig * 2;
            uint32_t o0, o1;
            pack_hl2(fmaxf(acc[i][j][0] + b1a, 0.f), fmaxf(acc[i][j][1] + b1a, 0.f), o0, o1);
            s_out[nloc * 128 + mloc]       = o0;
            s_out[(nloc + 1) * 128 + mloc] = o1;
            pack_hl2(fmaxf(acc[i][j][2] + b1b, 0.f), fmaxf(acc[i][j][3] + b1b, 0.f), o0, o1);
            s_out[nloc * 128 + mloc + 8]       = o0;
            s_out[(nloc + 1) * 128 + mloc + 8] = o1;
        }
    }
    __syncthreads();
#pragma unroll
    for (int t = 0; t < 8; ++t) {
        int f = tid + t * 256;
        int nloc = f >> 4, seg = f & 15;
        uint4 p0 = *(uint4*)(s_out + nloc * 128 + seg * 8);
        uint4 p1 = *(uint4*)(s_out + nloc * 128 + seg * 8 + 4);
        uint4 hq, lq;
        hq.x = (p0.x & 0xFFFFu) | (p0.y << 16);
        hq.y = (p0.z & 0xFFFFu) | (p0.w << 16);
        hq.z = (p1.x & 0xFFFFu) | (p1.y << 16);
        hq.w = (p1.z & 0xFFFFu) | (p1.w << 16);
        lq.x = (p0.x >> 16) | (p0.y & 0xFFFF0000u);
        lq.y = (p0.z >> 16) | (p0.w & 0xFFFF0000u);
        lq.z = (p1.x >> 16) | (p1.y & 0xFFFF0000u);
        lq.w = (p1.z >> 16) | (p1.w & 0xFFFF0000u);
        size_t dst = (size_t)(n0 + nloc) * 256 + m0 + seg * 8;
        *(uint4*)(g_x1h + dst) = hq;
        *(uint4*)(g_x1l + dst) = lq;
    }
}

// ================= conv2: frozen best config =================
#define STAGE_BYTES 65536
#define AH_OFF 0
#define AL_OFF 16384
#define BH_OFF 32768
#define BL_OFF 49152

#define LOADF(S, TB, KB) do { \
    _Pragma("unroll") \
    for (int i = 0; i < 4; ++i) { \
        int row = wm * 64 + i * 16 + a_row; \
        uint32_t ad = (TB) + swz(row * 128 + (KB) + a_hi); \
        ldsm4(ah##S[i], AH_OFF + ad); \
        ldsm4(al##S[i], AL_OFF + ad); \
    } \
    _Pragma("unroll") \
    for (int jp = 0; jp < 2; ++jp) { \
        int row = wn * 32 + jp * 16 + b_row; \
        uint32_t bd = (TB) + swz(row * 128 + (KB) + b_hi); \
        uint32_t t0[4], t1[4]; \
        ldsm4(t0, BH_OFF + bd); \
        ldsm4(t1, BL_OFF + bd); \
        bh##S[jp*2][0] = t0[0]; bh##S[jp*2][1] = t0[1]; \
        bh##S[jp*2+1][0] = t0[2]; bh##S[jp*2+1][1] = t0[3]; \
        bl##S[jp*2][0] = t1[0]; bl##S[jp*2][1] = t1[1]; \
        bl##S[jp*2+1][0] = t1[2]; bl##S[jp*2+1][1] = t1[3]; \
    } \
} while (0)

#define MMAF(S) do { \
    _Pragma("unroll") \
    for (int i = 0; i < 4; ++i) \
        _Pragma("unroll") \
        for (int j = 0; j < 4; ++j) { \
            mma16816(acc[i][j], ah##S[i], bh##S[j]); \
            mma16816(acc[i][j], ah##S[i], bl##S[j]); \
            mma16816(acc[i][j], al##S[i], bh##S[j]); \
        } \
} while (0)

__global__ __launch_bounds__(256, 1) void conv2_mma_kernel() {
    extern __shared__ char smem[];
    const uint32_t sb = smem_u32(smem) + 1024;
    int* base_n = (int*)smem;
    const int tid = threadIdx.x;
    const int wid = tid >> 5, lane = tid & 31;
    const int m0 = blockIdx.y * 128;
    const int n0 = blockIdx.x * 128;
    const int wm = wid & 1, wn = wid >> 1;

    if (tid < 128) {
        int n = n0 + tid;
        int b = n / 36, s = n - b * 36;
        int oh = s / 6, ow = s - oh * 6;
        base_n[tid] = b * 102400 + (oh * 40 + ow * 2) * 256;
    }
    __syncthreads();

    const int e_m = tid >> 3, e_seg = tid & 7;
    const int a_row = lane & 15, a_hi = (lane >> 4) << 4;
    const int b_row = ((lane >> 4) << 3) + (lane & 7), b_hi = ((lane >> 3) & 1) << 4;

    auto preload = [&](int cc) {
        const uint32_t tb = sb + (cc % 3) * STAGE_BYTES;
        const int khw = cc >> 2, icq = cc & 3;
        const int kh = khw / 9, kw = khw - kh * 9;
        const int boff = (kh * 20 + kw) * 256 + icq * 64;
#pragma unroll
        for (int p = 0; p < 4; ++p) {
            int row = e_m + p * 32;
            int sw = swz(row * 128 + e_seg * 16);
            size_t asrc = (size_t)(m0 + row) * KGEMM + cc * 64 + e_seg * 8;
            cpasync16(tb + AH_OFF + sw, g_w2h + asrc);
            cpasync16(tb + AL_OFF + sw, g_w2l + asrc);
            size_t bsrc = (size_t)base_n[row] + boff + e_seg * 8;
            cpasync16(tb + BH_OFF + sw, g_x1h + bsrc);
            cpasync16(tb + BL_OFF + sw, g_x1l + bsrc);
        }
        CP_COMMIT();
    };

    float acc[4][4][4];
#pragma unroll
    for (int i = 0; i < 4; ++i)
#pragma unroll
        for (int j = 0; j < 4; ++j)
#pragma unroll
            for (int r = 0; r < 4; ++r) acc[i][j][r] = 0.f;

    uint32_t ahA[4][4], alA[4][4], bhA[4][2], blA[4][2];
    uint32_t ahB[4][4], alB[4][4], bhB[4][2], blB[4][2];

    preload(0);
    preload(1);

    for (int c = 0; c < NCHUNK; ++c) {
        if (c + 2 < NCHUNK) { CP_WAIT(1); } else { CP_WAIT(0); }
        __syncthreads();
        if (c + 2 < NCHUNK) preload(c + 2);

        const uint32_t tb = sb + (c % 3) * STAGE_BYTES;
        LOADF(A, tb, 0);
        LOADF(B, tb, 32);
        MMAF(A);
        LOADF(A, tb, 64);
        MMAF(B);
        LOADF(B, tb, 96);
        MMAF(A);
        MMAF(B);
    }
    __syncthreads();

    float* s_y = (float*)(smem + 1024);
    const int gq = lane >> 2, tig = lane & 3;
#pragma unroll
    for (int i = 0; i < 4; ++i) {
        int mloc = wm * 64 + i * 16 + gq;
#pragma unroll
        for (int j = 0; j < 4; ++j) {
            int nloc = wn * 32 + j * 8 + tig * 2;
            s_y[nloc * 128 + mloc]           = acc[i][j][0];
            s_y[(nloc + 1) * 128 + mloc]     = acc[i][j][1];
            s_y[nloc * 128 + mloc + 8]       = acc[i][j][2];
            s_y[(nloc + 1) * 128 + mloc + 8] = acc[i][j][3];
        }
    }
    __syncthreads();
#pragma unroll
    for (int t = 0; t < 16; ++t) {
        int f = tid + t * 256;
        int nloc = f >> 5, seg = f & 31;
        float4 v = *(float4*)(s_y + nloc * 128 + seg * 4);
        *(float4*)(g_y2 + (size_t)(n0 + nloc) * 256 + m0 + seg * 4) = v;
    }
}

// ================= fused: squash + caps_up + routing (warp-owns-image step 3) =================
#define FR_WT   0                    // half[46080]  92160B
#define FR_UP   92160                // half[8*5760] 92160B
#define FR_U    184320               // float[8*288]  9216B
#define FR_PW   193536               // per-warp float[896]*8 = 28672B
#define FR_SMEM 222208

__global__ __launch_bounds__(256, 1) void fused_route_kernel(const float* __restrict__ b_route,
                                                             const float* __restrict__ b2) {
    extern __shared__ char sm[];
    __half* sWt = (__half*)(sm + FR_WT);
    __half* sUp = (__half*)(sm + FR_UP);
    float*  sU  = (float*)(sm + FR_U);
    const int tid = threadIdx.x;
    const int wid = tid >> 5, lane = tid & 31;
    const int g  = blockIdx.x >> 5;
    const int bt = blockIdx.x & 31;
    const int bimg = bt * 8 + wid;

    // 1. stage Wt (5760 uint4 = 92160B) — whole block
    {
        const uint4* src = (const uint4*)(g_wth + (size_t)g * 46080);
        uint4* dst = (uint4*)sWt;
        for (int f = tid; f < 5760; f += 256) dst[f] = src[f];
    }
    // 2. per-warp u = squash(y2 + b2), own warp's slice only
    {
        float b2v[8];
#pragma unroll
        for (int i = 0; i < 8; ++i) b2v[i] = __ldg(&b2[g * 8 + i]);
#pragma unroll
        for (int r = 0; r < 2; ++r) {
            int s = lane + 32 * r;
            if (s < 36) {
                const float* y = g_y2 + (size_t)(bimg * 36 + s) * 256 + g * 8;
                float4 y0 = *(const float4*)y;
                float4 y1 = *(const float4*)(y + 4);
                float u0 = y0.x + b2v[0], u1 = y0.y + b2v[1], u2 = y0.z + b2v[2], u3 = y0.w + b2v[3];
                float u4 = y1.x + b2v[4], u5 = y1.y + b2v[5], u6 = y1.z + b2v[6], u7 = y1.w + b2v[7];
                float l2 = u0*u0+u1*u1+u2*u2+u3*u3+u4*u4+u5*u5+u6*u6+u7*u7;
                float sc = squash_scale(l2);
                *(float4*)(sU + wid * 288 + s * 8)     = make_float4(u0*sc, u1*sc, u2*sc, u3*sc);
                *(float4*)(sU + wid * 288 + s * 8 + 4) = make_float4(u4*sc, u5*sc, u6*sc, u7*sc);
            }
        }
    }
    __syncthreads();   // sWt ready for all warps (own sU also ordered)

    // 3. up for OWN image: s-outer, u broadcast-loaded once per s
    {
        const float* uu = sU + wid * 288;
        __half* upd = sUp + wid * 5760;
        for (int s = 0; s < 36; ++s) {
            float4 ua = *(const float4*)(uu + s * 8);
            float4 ub = *(const float4*)(uu + s * 8 + 4);
            const __half* wrow = sWt + s * 1280;
#pragma unroll
            for (int q = 0; q < 5; ++q) {
                int j = lane + 32 * q;
                float d = dot8h(ua, ub, wrow + j * 8);
                upd[s * 160 + j] = __float2half(d);
            }
        }
    }
    __syncwarp();      // own sUp slice ready — no block barrier needed

    // 4. routing (own image)
    const __half* upw = sUp + wid * 5760;
    float* bb  = (float*)(sm + FR_PW) + wid * 896;
    float* cc  = bb + 360;
    float* vv  = cc + 360;
    float* nrm = vv + 160;

    {
        const float4* src = (const float4*)(b_route + g * 360);
#pragma unroll
        for (int r = 0; r < 3; ++r) {
            int f = lane + 32 * r;
            if (f < 90) ((float4*)bb)[f] = src[f];
        }
    }
    __syncwarp();

    float sv[5];
    for (int it = 0; it < 3; ++it) {
#pragma unroll
        for (int r = 0; r < 2; ++r) {
            int s = lane + 32 * r;
            if (s < 36) {
                float mx = -1e30f;
#pragma unroll
                for (int o = 0; o < OC; ++o) mx = fmaxf(mx, bb[s * 10 + o]);
                float e[OC]; float sum = 0.f;
#pragma unroll
                for (int o = 0; o < OC; ++o) { e[o] = __expf(bb[s * 10 + o] - mx); sum += e[o]; }
                float inv = __fdividef(1.f, sum);
#pragma unroll
                for (int o = 0; o < OC; ++o) cc[s * 10 + o] = e[o] * inv;
            }
        }
        __syncwarp();
#pragma unroll
        for (int q = 0; q < 5; ++q) {
            int od = lane + 32 * q;
            int o = od >> 4;
            float a = 0.f;
            for (int s = 0; s < 36; ++s)
                a = fmaf(cc[s * 10 + o], __half2float(upw[s * 160 + od]), a);
            sv[q] = a;
            vv[od] = a;
        }
        __syncwarp();
        if (lane < OC) {
            float l2 = 0.f;
#pragma unroll
            for (int d = 0; d < OD; ++d) { float x = vv[lane * 16 + d]; l2 += x * x; }
            nrm[lane] = squash_scale(l2);
        }
        __syncwarp();
#pragma unroll
        for (int q = 0; q < 5; ++q) {
            int od = lane + 32 * q;
            vv[od] = sv[q] * nrm[od >> 4];
        }
        __syncwarp();
        if (it < 2) {
#pragma unroll
            for (int r = 0; r < 12; ++r) {
                int e = lane + 32 * r;
                if (e < 360) {
                    int s = e / 10, o = e - s * 10;
                    const __half2* u2 = (const __half2*)(upw + s * 160 + o * 16);
                    float a = 0.f;
#pragma unroll
                    for (int d2 = 0; d2 < 8; ++d2) {
                        float2 uf = __half22float2(u2[d2]);
                        a = fmaf(uf.x, vv[o * 16 + d2 * 2], a);
                        a = fmaf(uf.y, vv[o * 16 + d2 * 2 + 1], a);
                    }
                    bb[e] += a;
                }
            }
            __syncwarp();
        }
    }
    float* dst = g_vg + (size_t)(bimg * G_NUM + g) * 160;
#pragma unroll
    for (int q = 0; q < 5; ++q) dst[lane + 32 * q] = vv[lane + 32 * q];
}

// ================= finalize =================
__global__ void finalize_kernel(float* __restrict__ out) {
    __shared__ float sv[OC * OD];
    const int b = blockIdx.x;
    const int tid = threadIdx.x;
    float a = 0.f;
    for (int g = 0; g < G_NUM; ++g)
        a += g_vg[(size_t)(b * G_NUM + g) * 160 + tid];
    out[b * 160 + tid] = a;
    sv[tid] = a;
    __syncthreads();
    if (tid < OC) {
        float l2 = 0.f;
#pragma unroll
        for (int d = 0; d < OD; ++d) { float x = sv[tid * 16 + d]; l2 += x * x; }
        out[B_SZ * 160 + b * OC + tid] = sqrtf(l2);
    }
}

// ================= launch =================
extern "C" void kernel_launch(void* const* d_in, const int* in_sizes, int n_in,
                              void* d_out, int out_size) {
    const float* inp     = (const float*)d_in[0];
    const float* W1      = (const float*)d_in[1];
    const float* b1      = (const float*)d_in[2];
    const float* W2      = (const float*)d_in[3];
    const float* b2      = (const float*)d_in[4];
    const float* Wcaps   = (const float*)d_in[5];
    const float* b_route = (const float*)d_in[6];
    float* out = (float*)d_out;

    const int w2_smem    = 20736 * 4;
    const int conv2_smem = 1024 + 3 * STAGE_BYTES;   // 197632
    cudaFuncSetAttribute(w2_convert_kernel, cudaFuncAttributeMaxDynamicSharedMemorySize, w2_smem);
    cudaFuncSetAttribute(conv1_mma_kernel,  cudaFuncAttributeMaxDynamicSharedMemorySize, C1_SMEM);
    cudaFuncSetAttribute(conv2_mma_kernel,  cudaFuncAttributeMaxDynamicSharedMemorySize, conv2_smem);
    cudaFuncSetAttribute(fused_route_kernel, cudaFuncAttributeMaxDynamicSharedMemorySize, FR_SMEM);

    static cudaStream_t s2 = nullptr;
    static cudaEvent_t evFork = nullptr, evJoin = nullptr;
    if (s2 == nullptr) {
        cudaStreamCreateWithFlags(&s2, cudaStreamNonBlocking);
        cudaEventCreateWithFlags(&evFork, cudaEventDisableTiming);
        cudaEventCreateWithFlags(&evJoin, cudaEventDisableTiming);
    }

    cudaEventRecord(evFork, 0);
    cudaStreamWaitEvent(s2, evFork, 0);
    w2_convert_kernel<<<C1, 256, w2_smem, s2>>>(W2);
    prep_wt<<<G_NUM * GS, 256, 0, s2>>>(Wcaps);
    cudaEventRecord(evJoin, s2);

    prep_w1<<<(C1 * 96 + 255) / 256, 256>>>(W1);
    dim3 g1(N1 / 128, 2);            // (800, 2)
    conv1_mma_kernel<<<g1, 256, C1_SMEM>>>(inp, b1);

    cudaStreamWaitEvent(0, evJoin, 0);
    dim3 g2(NGEMM / 128, 2);         // (72, 2)
    conv2_mma_kernel<<<g2, 256, conv2_smem>>>();

    fused_route_kernel<<<G_NUM * 32, 256, FR_SMEM>>>(b_route, b2);
    finalize_kernel<<<B_SZ, 160>>>(out);
}